// round 1
// baseline (speedup 1.0000x reference)
#include <cuda_runtime.h>
#include <cstdint>

#define BATCH 2
#define SEQ 2048
#define DMODEL 1024
#define NHEADS 16
#define DK 64
#define NTOK (BATCH*SEQ)          /* 4096 */
#define NEGVAL (-1000000000.0f)

// ---------------- scratch (device globals: allocation-free) ----------------
__device__ float g_q[(size_t)BATCH*NHEADS*SEQ*DK];   // 16 MB  [B,H,S,dk]
__device__ float g_k[(size_t)BATCH*NHEADS*SEQ*DK];   // 16 MB
__device__ float g_v[(size_t)BATCH*NHEADS*SEQ*DK];   // 16 MB
__device__ float g_ctx[(size_t)NTOK*DMODEL];         // 16 MB  [B,S,D]

// ============================================================================
// Projection GEMM: Y = X @ W^T + b, X [4096,1024], W [1024,1024] (row=out ch)
// 128x128 tile, 8x8 per thread, BK=16. Output scattered to [B,H,S,dk].
// ============================================================================
__global__ __launch_bounds__(256)
void k_proj(const float* __restrict__ X, const float* __restrict__ W,
            const float* __restrict__ bias, int which)
{
    float* out = (which == 0) ? g_q : (which == 1) ? g_k : g_v;
    __shared__ float As[16][132];
    __shared__ float Bs[16][132];
    const int tid = threadIdx.x;
    const int tx = tid & 15, ty = tid >> 4;
    const int row0 = blockIdx.x * 128;
    const int col0 = blockIdx.y * 128;
    float acc[8][8];
#pragma unroll
    for (int i = 0; i < 8; i++)
#pragma unroll
        for (int j = 0; j < 8; j++) acc[i][j] = 0.f;

    for (int k0 = 0; k0 < DMODEL; k0 += 16) {
#pragma unroll
        for (int l = 0; l < 2; l++) {
            int idx = tid + l * 256;          // 0..511
            int r = idx >> 2;                 // 0..127
            int c = (idx & 3) * 4;            // 0,4,8,12
            float4 xa = *(const float4*)&X[(size_t)(row0 + r) * DMODEL + k0 + c];
            As[c+0][r] = xa.x; As[c+1][r] = xa.y; As[c+2][r] = xa.z; As[c+3][r] = xa.w;
            float4 wa = *(const float4*)&W[(size_t)(col0 + r) * DMODEL + k0 + c];
            Bs[c+0][r] = wa.x; Bs[c+1][r] = wa.y; Bs[c+2][r] = wa.z; Bs[c+3][r] = wa.w;
        }
        __syncthreads();
#pragma unroll
        for (int kk = 0; kk < 16; kk++) {
            float4 a0 = *(const float4*)&As[kk][ty*8];
            float4 a1 = *(const float4*)&As[kk][ty*8+4];
            float4 b0 = *(const float4*)&Bs[kk][tx*8];
            float4 b1 = *(const float4*)&Bs[kk][tx*8+4];
            float a[8]  = {a0.x,a0.y,a0.z,a0.w,a1.x,a1.y,a1.z,a1.w};
            float bb[8] = {b0.x,b0.y,b0.z,b0.w,b1.x,b1.y,b1.z,b1.w};
#pragma unroll
            for (int i = 0; i < 8; i++)
#pragma unroll
                for (int j = 0; j < 8; j++) acc[i][j] += a[i] * bb[j];
        }
        __syncthreads();
    }
#pragma unroll
    for (int i = 0; i < 8; i++) {
        int n = row0 + ty*8 + i;
        int b = n >> 11, s = n & (SEQ - 1);
#pragma unroll
        for (int j = 0; j < 8; j++) {
            int o = col0 + tx*8 + j;
            int h = o >> 6, d = o & 63;
            out[(((size_t)(b*NHEADS + h))*SEQ + s)*DK + d] = acc[i][j] + bias[o];
        }
    }
}

// ============================================================================
// Output GEMM: out = g_ctx @ Wo^T + bo + residual   ([4096,1024])
// ============================================================================
__global__ __launch_bounds__(256)
void k_out(const float* __restrict__ W, const float* __restrict__ bias,
           const float* __restrict__ resid, float* __restrict__ out)
{
    __shared__ float As[16][132];
    __shared__ float Bs[16][132];
    const int tid = threadIdx.x;
    const int tx = tid & 15, ty = tid >> 4;
    const int row0 = blockIdx.x * 128;
    const int col0 = blockIdx.y * 128;
    float acc[8][8];
#pragma unroll
    for (int i = 0; i < 8; i++)
#pragma unroll
        for (int j = 0; j < 8; j++) acc[i][j] = 0.f;

    for (int k0 = 0; k0 < DMODEL; k0 += 16) {
#pragma unroll
        for (int l = 0; l < 2; l++) {
            int idx = tid + l * 256;
            int r = idx >> 2;
            int c = (idx & 3) * 4;
            float4 xa = *(const float4*)&g_ctx[(size_t)(row0 + r) * DMODEL + k0 + c];
            As[c+0][r] = xa.x; As[c+1][r] = xa.y; As[c+2][r] = xa.z; As[c+3][r] = xa.w;
            float4 wa = *(const float4*)&W[(size_t)(col0 + r) * DMODEL + k0 + c];
            Bs[c+0][r] = wa.x; Bs[c+1][r] = wa.y; Bs[c+2][r] = wa.z; Bs[c+3][r] = wa.w;
        }
        __syncthreads();
#pragma unroll
        for (int kk = 0; kk < 16; kk++) {
            float4 a0 = *(const float4*)&As[kk][ty*8];
            float4 a1 = *(const float4*)&As[kk][ty*8+4];
            float4 b0 = *(const float4*)&Bs[kk][tx*8];
            float4 b1 = *(const float4*)&Bs[kk][tx*8+4];
            float a[8]  = {a0.x,a0.y,a0.z,a0.w,a1.x,a1.y,a1.z,a1.w};
            float bb[8] = {b0.x,b0.y,b0.z,b0.w,b1.x,b1.y,b1.z,b1.w};
#pragma unroll
            for (int i = 0; i < 8; i++)
#pragma unroll
                for (int j = 0; j < 8; j++) acc[i][j] += a[i] * bb[j];
        }
        __syncthreads();
    }
#pragma unroll
    for (int i = 0; i < 8; i++) {
        int n = row0 + ty*8 + i;
#pragma unroll
        for (int j = 0; j < 8; j++) {
            int o = col0 + tx*8 + j;
            size_t idx = (size_t)n * DMODEL + o;
            out[idx] = acc[i][j] + bias[o] + resid[idx];
        }
    }
}

// ============================================================================
// Scores: per (b,h): S = (q @ k^T) * 0.125, mask -> NEG. Write to d_out.
// 128x128 tile, 8x8/thread, K=64 in 2 chunks of 32.
// ============================================================================
__global__ __launch_bounds__(256)
void k_scores(const unsigned char* __restrict__ mask, float* __restrict__ scores)
{
    const int bh = blockIdx.z;
    const int b = bh >> 4;
    const float* q  = g_q + (size_t)bh * SEQ * DK;
    const float* km = g_k + (size_t)bh * SEQ * DK;
    const int qr0 = blockIdx.y * 128;
    const int kr0 = blockIdx.x * 128;
    __shared__ float Qs[32][132];
    __shared__ float Ks[32][132];
    const int tid = threadIdx.x;
    const int tx = tid & 15, ty = tid >> 4;
    float acc[8][8];
#pragma unroll
    for (int i = 0; i < 8; i++)
#pragma unroll
        for (int j = 0; j < 8; j++) acc[i][j] = 0.f;

    for (int k0 = 0; k0 < DK; k0 += 32) {
#pragma unroll
        for (int l = 0; l < 4; l++) {
            int idx = tid + l * 256;        // 0..1023
            int r = idx >> 3;               // 0..127
            int c = (idx & 7) * 4;          // 0..28
            float4 qa = *(const float4*)&q[(size_t)(qr0 + r) * DK + k0 + c];
            Qs[c+0][r] = qa.x; Qs[c+1][r] = qa.y; Qs[c+2][r] = qa.z; Qs[c+3][r] = qa.w;
            float4 ka = *(const float4*)&km[(size_t)(kr0 + r) * DK + k0 + c];
            Ks[c+0][r] = ka.x; Ks[c+1][r] = ka.y; Ks[c+2][r] = ka.z; Ks[c+3][r] = ka.w;
        }
        __syncthreads();
#pragma unroll
        for (int kk = 0; kk < 32; kk++) {
            float4 a0 = *(const float4*)&Qs[kk][ty*8];
            float4 a1 = *(const float4*)&Qs[kk][ty*8+4];
            float4 b0 = *(const float4*)&Ks[kk][tx*8];
            float4 b1 = *(const float4*)&Ks[kk][tx*8+4];
            float a[8]  = {a0.x,a0.y,a0.z,a0.w,a1.x,a1.y,a1.z,a1.w};
            float bb[8] = {b0.x,b0.y,b0.z,b0.w,b1.x,b1.y,b1.z,b1.w};
#pragma unroll
            for (int i = 0; i < 8; i++)
#pragma unroll
                for (int j = 0; j < 8; j++) acc[i][j] += a[i] * bb[j];
        }
        __syncthreads();
    }
#pragma unroll
    for (int i = 0; i < 8; i++) {
        int qi = qr0 + ty*8 + i;
        size_t orow = ((size_t)bh * SEQ + qi) * SEQ;
        const unsigned char* mrow = mask + ((size_t)b * SEQ + qi) * SEQ;
#pragma unroll
        for (int j = 0; j < 8; j++) {
            int kj = kr0 + tx*8 + j;
            float v = acc[i][j] * 0.125f;   // 1/sqrt(64)
            if (mrow[kj]) v = NEGVAL;
            scores[orow + kj] = v;
        }
    }
}

// ============================================================================
// Softmax: one block per row of 2048. Row lives in 8 regs/thread.
// ============================================================================
__global__ __launch_bounds__(256)
void k_softmax(const float* __restrict__ scores, float* __restrict__ attn)
{
    const size_t row = blockIdx.x;
    const float4* src = (const float4*)(scores + row * SEQ);
    float4* dst = (float4*)(attn + row * SEQ);
    const int tid = threadIdx.x;
    float4 v0 = src[tid];
    float4 v1 = src[tid + 256];
    float m = fmaxf(fmaxf(fmaxf(v0.x, v0.y), fmaxf(v0.z, v0.w)),
                    fmaxf(fmaxf(v1.x, v1.y), fmaxf(v1.z, v1.w)));
    __shared__ float red[8];
#pragma unroll
    for (int off = 16; off; off >>= 1) m = fmaxf(m, __shfl_xor_sync(0xffffffffu, m, off));
    if ((tid & 31) == 0) red[tid >> 5] = m;
    __syncthreads();
    if (tid < 32) {
        float t = (tid < 8) ? red[tid] : -3.4e38f;
#pragma unroll
        for (int off = 4; off; off >>= 1) t = fmaxf(t, __shfl_xor_sync(0xffffffffu, t, off));
        if (tid == 0) red[0] = t;
    }
    __syncthreads();
    const float bm = red[0];
    __syncthreads();                      // everyone read red[0] before reuse
    v0.x = __expf(v0.x - bm); v0.y = __expf(v0.y - bm);
    v0.z = __expf(v0.z - bm); v0.w = __expf(v0.w - bm);
    v1.x = __expf(v1.x - bm); v1.y = __expf(v1.y - bm);
    v1.z = __expf(v1.z - bm); v1.w = __expf(v1.w - bm);
    float s = v0.x + v0.y + v0.z + v0.w + v1.x + v1.y + v1.z + v1.w;
#pragma unroll
    for (int off = 16; off; off >>= 1) s += __shfl_xor_sync(0xffffffffu, s, off);
    if ((tid & 31) == 0) red[tid >> 5] = s;
    __syncthreads();
    if (tid < 32) {
        float t = (tid < 8) ? red[tid] : 0.f;
#pragma unroll
        for (int off = 4; off; off >>= 1) t += __shfl_xor_sync(0xffffffffu, t, off);
        if (tid == 0) red[0] = t;
    }
    __syncthreads();
    const float inv = 1.0f / red[0];
    v0.x *= inv; v0.y *= inv; v0.z *= inv; v0.w *= inv;
    v1.x *= inv; v1.y *= inv; v1.z *= inv; v1.w *= inv;
    dst[tid] = v0;
    dst[tid + 256] = v1;
}

// ============================================================================
// A@V: per (b,h): ctx = attn(2048x2048) @ v(2048x64). 128x64 tile, 8x4/thread.
// ============================================================================
__global__ __launch_bounds__(256)
void k_av(const float* __restrict__ attn)
{
    const int bh = blockIdx.z;
    const int b = bh >> 4, h = bh & 15;
    const int qr0 = blockIdx.x * 128;
    const float* A = attn + (size_t)bh * SEQ * SEQ;
    const float* V = g_v + (size_t)bh * SEQ * DK;
    __shared__ float As[32][132];   // [k][qrow]
    __shared__ float Vs[32][68];    // [k][d]
    const int tid = threadIdx.x;
    const int tx = tid & 15, ty = tid >> 4;
    float acc[8][4];
#pragma unroll
    for (int i = 0; i < 8; i++)
#pragma unroll
        for (int j = 0; j < 4; j++) acc[i][j] = 0.f;

    for (int k0 = 0; k0 < SEQ; k0 += 32) {
#pragma unroll
        for (int l = 0; l < 4; l++) {
            int idx = tid + l * 256;        // 0..1023
            int r = idx >> 3;               // 0..127
            int c = (idx & 7) * 4;          // 0..28
            float4 aa = *(const float4*)&A[(size_t)(qr0 + r) * SEQ + k0 + c];
            As[c+0][r] = aa.x; As[c+1][r] = aa.y; As[c+2][r] = aa.z; As[c+3][r] = aa.w;
        }
#pragma unroll
        for (int l = 0; l < 2; l++) {
            int idx = tid + l * 256;        // 0..511
            int r = idx >> 4;               // 0..31
            int c = (idx & 15) * 4;         // 0..60
            float4 va = *(const float4*)&V[(size_t)(k0 + r) * DK + c];
            *(float4*)&Vs[r][c] = va;
        }
        __syncthreads();
#pragma unroll
        for (int kk = 0; kk < 32; kk++) {
            float4 a0 = *(const float4*)&As[kk][ty*8];
            float4 a1 = *(const float4*)&As[kk][ty*8+4];
            float4 bv = *(const float4*)&Vs[kk][tx*4];
            float a[8]  = {a0.x,a0.y,a0.z,a0.w,a1.x,a1.y,a1.z,a1.w};
            float bb[4] = {bv.x,bv.y,bv.z,bv.w};
#pragma unroll
            for (int i = 0; i < 8; i++)
#pragma unroll
                for (int j = 0; j < 4; j++) acc[i][j] += a[i] * bb[j];
        }
        __syncthreads();
    }
#pragma unroll
    for (int i = 0; i < 8; i++) {
        int s = qr0 + ty*8 + i;
        float4 w;
        w.x = acc[i][0]; w.y = acc[i][1]; w.z = acc[i][2]; w.w = acc[i][3];
        *(float4*)&g_ctx[((size_t)(b * SEQ + s)) * DMODEL + h * DK + tx*4] = w;
    }
}

// ============================================================================
extern "C" void kernel_launch(void* const* d_in, const int* in_sizes, int n_in,
                              void* d_out, int out_size)
{
    const float* Q  = (const float*)d_in[0];
    const float* K  = (const float*)d_in[1];
    const float* V  = (const float*)d_in[2];
    const unsigned char* mask = (const unsigned char*)d_in[3];
    const float* Wq = (const float*)d_in[4];  const float* bq = (const float*)d_in[5];
    const float* Wk = (const float*)d_in[6];  const float* bk = (const float*)d_in[7];
    const float* Wv = (const float*)d_in[8];  const float* bv = (const float*)d_in[9];
    const float* Wo = (const float*)d_in[10]; const float* bo = (const float*)d_in[11];

    float* out    = (float*)d_out;                                  // [B,S,D]
    float* attn   = out + (size_t)NTOK * DMODEL;                    // [B,H,S,S]
    float* scores = attn + (size_t)BATCH * NHEADS * SEQ * SEQ;      // [B,H,S,S]

    dim3 gp(NTOK / 128, DMODEL / 128);          // 32 x 8
    k_proj<<<gp, 256>>>(Q, Wq, bq, 0);
    k_proj<<<gp, 256>>>(K, Wk, bk, 1);
    k_proj<<<gp, 256>>>(V, Wv, bv, 2);

    dim3 gs(SEQ / 128, SEQ / 128, BATCH * NHEADS);  // 16 x 16 x 32
    k_scores<<<gs, 256>>>(mask, scores);

    k_softmax<<<BATCH * NHEADS * SEQ, 256>>>(scores, attn);

    dim3 ga(SEQ / 128, 1, BATCH * NHEADS);          // 16 x 1 x 32
    k_av<<<ga, 256>>>(attn);

    k_out<<<gp, 256>>>(Wo, bo, Q, out);
}

// round 2
// speedup vs baseline: 1.0504x; 1.0504x over previous
#include <cuda_runtime.h>
#include <cstdint>

#define BATCH 2
#define SEQ 2048
#define DMODEL 1024
#define NHEADS 16
#define DK 64
#define NTOK (BATCH*SEQ)          /* 4096 */
#define NEGVAL (-1000000000.0f)

// ---------------- scratch (device globals: allocation-free) ----------------
__device__ float g_q[(size_t)BATCH*NHEADS*SEQ*DK];   // 16 MB  [B,H,S,dk]
__device__ float g_k[(size_t)BATCH*NHEADS*SEQ*DK];   // 16 MB
__device__ float g_v[(size_t)BATCH*NHEADS*SEQ*DK];   // 16 MB
__device__ float g_ctx[(size_t)NTOK*DMODEL];         // 16 MB  [B,S,D]

// ============================================================================
// Projection GEMM: Y = X @ W^T + b, X [4096,1024], W [1024,1024] (row=out ch)
// 128x128 tile, 8x8 per thread, BK=16. Output scattered to [B,H,S,dk].
// ============================================================================
__global__ __launch_bounds__(256)
void k_proj(const float* __restrict__ X, const float* __restrict__ W,
            const float* __restrict__ bias, int which)
{
    float* out = (which == 0) ? g_q : (which == 1) ? g_k : g_v;
    __shared__ float As[16][132];
    __shared__ float Bs[16][132];
    const int tid = threadIdx.x;
    const int tx = tid & 15, ty = tid >> 4;
    const int row0 = blockIdx.x * 128;
    const int col0 = blockIdx.y * 128;
    float acc[8][8];
#pragma unroll
    for (int i = 0; i < 8; i++)
#pragma unroll
        for (int j = 0; j < 8; j++) acc[i][j] = 0.f;

    for (int k0 = 0; k0 < DMODEL; k0 += 16) {
#pragma unroll
        for (int l = 0; l < 2; l++) {
            int idx = tid + l * 256;          // 0..511
            int r = idx >> 2;                 // 0..127
            int c = (idx & 3) * 4;            // 0,4,8,12
            float4 xa = *(const float4*)&X[(size_t)(row0 + r) * DMODEL + k0 + c];
            As[c+0][r] = xa.x; As[c+1][r] = xa.y; As[c+2][r] = xa.z; As[c+3][r] = xa.w;
            float4 wa = *(const float4*)&W[(size_t)(col0 + r) * DMODEL + k0 + c];
            Bs[c+0][r] = wa.x; Bs[c+1][r] = wa.y; Bs[c+2][r] = wa.z; Bs[c+3][r] = wa.w;
        }
        __syncthreads();
#pragma unroll
        for (int kk = 0; kk < 16; kk++) {
            float4 a0 = *(const float4*)&As[kk][ty*8];
            float4 a1 = *(const float4*)&As[kk][ty*8+4];
            float4 b0 = *(const float4*)&Bs[kk][tx*8];
            float4 b1 = *(const float4*)&Bs[kk][tx*8+4];
            float a[8]  = {a0.x,a0.y,a0.z,a0.w,a1.x,a1.y,a1.z,a1.w};
            float bb[8] = {b0.x,b0.y,b0.z,b0.w,b1.x,b1.y,b1.z,b1.w};
#pragma unroll
            for (int i = 0; i < 8; i++)
#pragma unroll
                for (int j = 0; j < 8; j++) acc[i][j] += a[i] * bb[j];
        }
        __syncthreads();
    }
#pragma unroll
    for (int i = 0; i < 8; i++) {
        int n = row0 + ty*8 + i;
        int b = n >> 11, s = n & (SEQ - 1);
#pragma unroll
        for (int j = 0; j < 8; j++) {
            int o = col0 + tx*8 + j;
            int h = o >> 6, d = o & 63;
            out[(((size_t)(b*NHEADS + h))*SEQ + s)*DK + d] = acc[i][j] + bias[o];
        }
    }
}

// ============================================================================
// Output GEMM: out = g_ctx @ Wo^T + bo + residual   ([4096,1024])
// ============================================================================
__global__ __launch_bounds__(256)
void k_out(const float* __restrict__ W, const float* __restrict__ bias,
           const float* __restrict__ resid, float* __restrict__ out)
{
    __shared__ float As[16][132];
    __shared__ float Bs[16][132];
    const int tid = threadIdx.x;
    const int tx = tid & 15, ty = tid >> 4;
    const int row0 = blockIdx.x * 128;
    const int col0 = blockIdx.y * 128;
    float acc[8][8];
#pragma unroll
    for (int i = 0; i < 8; i++)
#pragma unroll
        for (int j = 0; j < 8; j++) acc[i][j] = 0.f;

    for (int k0 = 0; k0 < DMODEL; k0 += 16) {
#pragma unroll
        for (int l = 0; l < 2; l++) {
            int idx = tid + l * 256;
            int r = idx >> 2;
            int c = (idx & 3) * 4;
            float4 xa = *(const float4*)&g_ctx[(size_t)(row0 + r) * DMODEL + k0 + c];
            As[c+0][r] = xa.x; As[c+1][r] = xa.y; As[c+2][r] = xa.z; As[c+3][r] = xa.w;
            float4 wa = *(const float4*)&W[(size_t)(col0 + r) * DMODEL + k0 + c];
            Bs[c+0][r] = wa.x; Bs[c+1][r] = wa.y; Bs[c+2][r] = wa.z; Bs[c+3][r] = wa.w;
        }
        __syncthreads();
#pragma unroll
        for (int kk = 0; kk < 16; kk++) {
            float4 a0 = *(const float4*)&As[kk][ty*8];
            float4 a1 = *(const float4*)&As[kk][ty*8+4];
            float4 b0 = *(const float4*)&Bs[kk][tx*8];
            float4 b1 = *(const float4*)&Bs[kk][tx*8+4];
            float a[8]  = {a0.x,a0.y,a0.z,a0.w,a1.x,a1.y,a1.z,a1.w};
            float bb[8] = {b0.x,b0.y,b0.z,b0.w,b1.x,b1.y,b1.z,b1.w};
#pragma unroll
            for (int i = 0; i < 8; i++)
#pragma unroll
                for (int j = 0; j < 8; j++) acc[i][j] += a[i] * bb[j];
        }
        __syncthreads();
    }
#pragma unroll
    for (int i = 0; i < 8; i++) {
        int n = row0 + ty*8 + i;
#pragma unroll
        for (int j = 0; j < 8; j++) {
            int o = col0 + tx*8 + j;
            size_t idx = (size_t)n * DMODEL + o;
            out[idx] = acc[i][j] + bias[o] + resid[idx];
        }
    }
}

// ============================================================================
// Fused attention: per (bh, 128-q-row block):
//  pass A: scores = (q@k^T)*0.125 masked -> write scores; online rowmax/rowsum
//  pass B: re-read scores (L2-hot), attn = exp(s-m)/l -> write attn; ctx += attn@V
// smem union: passA {Qs[64][132], Ks[64][132]}  passB {Es[128][132], Vs[128][68]}
// ============================================================================
#define SMEM_FLOATS (2*64*132 + 128*68)   /* 16896 + 8704 = 25600 floats */

__global__ __launch_bounds__(256, 2)
void k_attn(const unsigned char* __restrict__ mask,
            float* __restrict__ scores_g, float* __restrict__ attn_g)
{
    extern __shared__ float sm[];
    float* Qs = sm;                 // [64][132]
    float* Ks = sm + 64*132;        // [64][132]
    float* Es = sm;                 // [128][132]  (reuses Qs+Ks exactly)
    float* Vs = sm + 2*64*132;      // [128][68]

    const int tid = threadIdx.x;
    const int tx = tid & 15, ty = tid >> 4;
    const int qb = blockIdx.x, bh = blockIdx.y;
    const int b = bh >> 4, h = bh & 15;
    const int qr0 = qb * 128;
    const float* qp = g_q + (size_t)bh * SEQ * DK;
    const float* kp = g_k + (size_t)bh * SEQ * DK;
    const float* vp = g_v + (size_t)bh * SEQ * DK;
    float* srow = scores_g + ((size_t)bh * SEQ + qr0) * SEQ;
    float* arow = attn_g   + ((size_t)bh * SEQ + qr0) * SEQ;

    // ---- load Q tile once: Qs[dk][row] ----
#pragma unroll
    for (int l = 0; l < 8; l++) {
        int idx = tid + l * 256;
        int r = idx >> 4, c = (idx & 15) * 4;
        float4 qa = *(const float4*)&qp[(size_t)(qr0 + r) * DK + c];
        Qs[(c+0)*132 + r] = qa.x; Qs[(c+1)*132 + r] = qa.y;
        Qs[(c+2)*132 + r] = qa.z; Qs[(c+3)*132 + r] = qa.w;
    }

    float m[8], lsum[8];
#pragma unroll
    for (int i = 0; i < 8; i++) { m[i] = -3.0e38f; lsum[i] = 0.f; }

    // ================= PASS A =================
    for (int kt = 0; kt < 16; kt++) {
        __syncthreads();
#pragma unroll
        for (int l = 0; l < 8; l++) {
            int idx = tid + l * 256;
            int r = idx >> 4, c = (idx & 15) * 4;
            float4 ka = *(const float4*)&kp[(size_t)(kt*128 + r) * DK + c];
            Ks[(c+0)*132 + r] = ka.x; Ks[(c+1)*132 + r] = ka.y;
            Ks[(c+2)*132 + r] = ka.z; Ks[(c+3)*132 + r] = ka.w;
        }
        __syncthreads();

        float acc[8][8];
#pragma unroll
        for (int i = 0; i < 8; i++)
#pragma unroll
            for (int j = 0; j < 8; j++) acc[i][j] = 0.f;

#pragma unroll 16
        for (int kk = 0; kk < 64; kk++) {
            float4 a0 = *(const float4*)&Qs[kk*132 + ty*8];
            float4 a1 = *(const float4*)&Qs[kk*132 + ty*8 + 4];
            float4 b0 = *(const float4*)&Ks[kk*132 + tx*8];
            float4 b1 = *(const float4*)&Ks[kk*132 + tx*8 + 4];
            float a[8]  = {a0.x,a0.y,a0.z,a0.w,a1.x,a1.y,a1.z,a1.w};
            float bb[8] = {b0.x,b0.y,b0.z,b0.w,b1.x,b1.y,b1.z,b1.w};
#pragma unroll
            for (int i = 0; i < 8; i++)
#pragma unroll
                for (int j = 0; j < 8; j++) acc[i][j] += a[i] * bb[j];
        }

        // epilogue: scale, mask, store scores, online softmax stats
#pragma unroll
        for (int i = 0; i < 8; i++) {
            int qi = qr0 + ty*8 + i;
            const unsigned char* mrow =
                mask + ((size_t)b * SEQ + qi) * SEQ + kt*128 + tx*8;
            uint2 mk = *(const uint2*)mrow;
            float v[8];
#pragma unroll
            for (int j = 0; j < 8; j++) {
                unsigned byte = ((j < 4 ? mk.x >> (8*j) : mk.y >> (8*(j-4))) & 0xffu);
                v[j] = byte ? NEGVAL : acc[i][j] * 0.125f;
            }
            float* sp = &srow[(size_t)(ty*8 + i) * SEQ + kt*128 + tx*8];
            *(float4*)sp       = make_float4(v[0], v[1], v[2], v[3]);
            *(float4*)(sp + 4) = make_float4(v[4], v[5], v[6], v[7]);

            float tm = v[0];
#pragma unroll
            for (int j = 1; j < 8; j++) tm = fmaxf(tm, v[j]);
#pragma unroll
            for (int off = 1; off < 16; off <<= 1)
                tm = fmaxf(tm, __shfl_xor_sync(0xffffffffu, tm, off));
            float nm = fmaxf(m[i], tm);
            float ts = 0.f;
#pragma unroll
            for (int j = 0; j < 8; j++) ts += __expf(v[j] - nm);
#pragma unroll
            for (int off = 1; off < 16; off <<= 1)
                ts += __shfl_xor_sync(0xffffffffu, ts, off);
            lsum[i] = lsum[i] * __expf(m[i] - nm) + ts;
            m[i] = nm;
        }
    }

    float inv[8];
#pragma unroll
    for (int i = 0; i < 8; i++) inv[i] = 1.0f / lsum[i];

    // ================= PASS B =================
    float acc2[8][4];
#pragma unroll
    for (int i = 0; i < 8; i++)
#pragma unroll
        for (int j = 0; j < 4; j++) acc2[i][j] = 0.f;

    for (int kt = 15; kt >= 0; kt--) {      // reverse: LIFO L2 locality
        __syncthreads();
        // load V tile: Vs[krow][d]
#pragma unroll
        for (int l = 0; l < 8; l++) {
            int idx = tid + l * 256;
            int r = idx >> 4, c = (idx & 15) * 4;
            float4 va = *(const float4*)&vp[(size_t)(kt*128 + r) * DK + c];
            *(float4*)&Vs[r*68 + c] = va;
        }
        // e = exp(s-m)*inv ; write attn ; stage Es[kcol][row]
#pragma unroll
        for (int ig = 0; ig < 2; ig++) {
            float er[4][8];
#pragma unroll
            for (int ii = 0; ii < 4; ii++) {
                int i = ig*4 + ii;
                const float* sp = &srow[(size_t)(ty*8 + i) * SEQ + kt*128 + tx*8];
                float4 s0 = *(const float4*)sp;
                float4 s1 = *(const float4*)(sp + 4);
                float mi = m[i], iv = inv[i];
                er[ii][0] = __expf(s0.x - mi) * iv;
                er[ii][1] = __expf(s0.y - mi) * iv;
                er[ii][2] = __expf(s0.z - mi) * iv;
                er[ii][3] = __expf(s0.w - mi) * iv;
                er[ii][4] = __expf(s1.x - mi) * iv;
                er[ii][5] = __expf(s1.y - mi) * iv;
                er[ii][6] = __expf(s1.z - mi) * iv;
                er[ii][7] = __expf(s1.w - mi) * iv;
                float* ap = &arow[(size_t)(ty*8 + i) * SEQ + kt*128 + tx*8];
                *(float4*)ap       = make_float4(er[ii][0], er[ii][1], er[ii][2], er[ii][3]);
                *(float4*)(ap + 4) = make_float4(er[ii][4], er[ii][5], er[ii][6], er[ii][7]);
            }
#pragma unroll
            for (int j = 0; j < 8; j++) {
                *(float4*)&Es[(tx*8 + j)*132 + ty*8 + ig*4] =
                    make_float4(er[0][j], er[1][j], er[2][j], er[3][j]);
            }
        }
        __syncthreads();

#pragma unroll 16
        for (int kk = 0; kk < 128; kk++) {
            float4 a0 = *(const float4*)&Es[kk*132 + ty*8];
            float4 a1 = *(const float4*)&Es[kk*132 + ty*8 + 4];
            float4 bv = *(const float4*)&Vs[kk*68 + tx*4];
            float a[8]  = {a0.x,a0.y,a0.z,a0.w,a1.x,a1.y,a1.z,a1.w};
            float bb[4] = {bv.x,bv.y,bv.z,bv.w};
#pragma unroll
            for (int i = 0; i < 8; i++)
#pragma unroll
                for (int j = 0; j < 4; j++) acc2[i][j] += a[i] * bb[j];
        }
    }

    // write ctx [B,S,D]
#pragma unroll
    for (int i = 0; i < 8; i++) {
        int s = qr0 + ty*8 + i;
        *(float4*)&g_ctx[((size_t)(b * SEQ + s)) * DMODEL + h*DK + tx*4] =
            make_float4(acc2[i][0], acc2[i][1], acc2[i][2], acc2[i][3]);
    }
}

// ============================================================================
extern "C" void kernel_launch(void* const* d_in, const int* in_sizes, int n_in,
                              void* d_out, int out_size)
{
    const float* Q  = (const float*)d_in[0];
    const float* K  = (const float*)d_in[1];
    const float* V  = (const float*)d_in[2];
    const unsigned char* mask = (const unsigned char*)d_in[3];
    const float* Wq = (const float*)d_in[4];  const float* bq = (const float*)d_in[5];
    const float* Wk = (const float*)d_in[6];  const float* bk = (const float*)d_in[7];
    const float* Wv = (const float*)d_in[8];  const float* bv = (const float*)d_in[9];
    const float* Wo = (const float*)d_in[10]; const float* bo = (const float*)d_in[11];

    float* out    = (float*)d_out;                                  // [B,S,D]
    float* attn   = out + (size_t)NTOK * DMODEL;                    // [B,H,S,S]
    float* scores = attn + (size_t)BATCH * NHEADS * SEQ * SEQ;      // [B,H,S,S]

    static const size_t attn_smem = SMEM_FLOATS * sizeof(float);    // 102400 B
    cudaFuncSetAttribute(k_attn, cudaFuncAttributeMaxDynamicSharedMemorySize,
                         (int)attn_smem);

    dim3 gp(NTOK / 128, DMODEL / 128);          // 32 x 8
    k_proj<<<gp, 256>>>(Q, Wq, bq, 0);
    k_proj<<<gp, 256>>>(K, Wk, bk, 1);
    k_proj<<<gp, 256>>>(V, Wv, bv, 2);

    dim3 gf(SEQ / 128, BATCH * NHEADS);         // 16 x 32
    k_attn<<<gf, 256, attn_smem>>>(mask, scores, attn);

    k_out<<<gp, 256>>>(Wo, bo, Q, out);
}

// round 4
// speedup vs baseline: 1.1597x; 1.1041x over previous
#include <cuda_runtime.h>
#include <cstdint>

#define BATCH 2
#define SEQ 2048
#define DMODEL 1024
#define NHEADS 16
#define DK 64
#define NTOK (BATCH*SEQ)          /* 4096 */
#define NEGVAL (-1000000000.0f)

// ---------------- scratch (device globals: allocation-free) ----------------
__device__ float g_q[(size_t)BATCH*NHEADS*SEQ*DK];   // 16 MB  [B,H,S,dk]
__device__ float g_k[(size_t)BATCH*NHEADS*SEQ*DK];   // 16 MB
__device__ float g_v[(size_t)BATCH*NHEADS*SEQ*DK];   // 16 MB
__device__ float g_ctx[(size_t)NTOK*DMODEL];         // 16 MB  [B,S,D]

// ============================ mma.sync helpers ==============================
__device__ __forceinline__ uint32_t cvt_tf32(float x) {
    uint32_t r; asm("cvt.rna.tf32.f32 %0, %1;" : "=r"(r) : "f"(x)); return r;
}
__device__ __forceinline__ void mma8(float* c, const uint32_t* a, const uint32_t* b) {
    asm volatile("mma.sync.aligned.m16n8k8.row.col.f32.tf32.tf32.f32 "
                 "{%0,%1,%2,%3}, {%4,%5,%6,%7}, {%8,%9}, {%0,%1,%2,%3};"
                 : "+f"(c[0]), "+f"(c[1]), "+f"(c[2]), "+f"(c[3])
                 : "r"(a[0]), "r"(a[1]), "r"(a[2]), "r"(a[3]),
                   "r"(b[0]), "r"(b[1]));
}

// ==================== tf32 3x GEMM core (HMMA path) =========================
// C[128,128] = A[row0:+128, 0:1024] @ B[col0:+128, 0:1024]^T
// smem tiles: row-stride 20 (16 data + 4 pad) -> conflict-free frag loads.
#define RS 20
#define TILE_U32 (128*RS)

struct GemmSmem {
    uint32_t Ah[TILE_U32];
    uint32_t Al[TILE_U32];
    uint32_t Bh[TILE_U32];
    uint32_t Bl[TILE_U32];
};

// acc layout: acc[mt][nt][4] ; mt 0..3 (16-row tiles), nt 0..3 (8-col tiles)
__device__ __forceinline__ void gemm_tf32x3(
    const float* __restrict__ A, const float* __restrict__ B,
    int row0, int col0, GemmSmem* sm, float acc[4][4][4])
{
    const int tid = threadIdx.x;
    const int wid = tid >> 5, lane = tid & 31;
    const int g = lane >> 2, tig = lane & 3;
    const int warp_m = wid & 1;          // 0..1  (64 rows each)
    const int warp_n = wid >> 1;         // 0..3  (32 cols each)
    const int rA = warp_m * 64;
    const int cB = warp_n * 32;

#pragma unroll
    for (int mt = 0; mt < 4; mt++)
#pragma unroll
        for (int nt = 0; nt < 4; nt++)
#pragma unroll
            for (int q = 0; q < 4; q++) acc[mt][nt][q] = 0.f;

    for (int it = 0; it < DMODEL / 16; it++) {
        const int k0 = it * 16;
        __syncthreads();
        // ---- load + split A tile (128x16) and B tile (128x16) ----
#pragma unroll
        for (int l = 0; l < 2; l++) {
            int idx = tid + l * 256;          // 0..511
            int r = idx >> 2;                 // 0..127
            int c4 = (idx & 3) * 4;           // 0,4,8,12
            float4 x = *(const float4*)&A[(size_t)(row0 + r) * DMODEL + k0 + c4];
            uint32_t h0 = cvt_tf32(x.x), h1 = cvt_tf32(x.y),
                     h2 = cvt_tf32(x.z), h3 = cvt_tf32(x.w);
            uint32_t l0 = cvt_tf32(x.x - __uint_as_float(h0));
            uint32_t l1 = cvt_tf32(x.y - __uint_as_float(h1));
            uint32_t l2 = cvt_tf32(x.z - __uint_as_float(h2));
            uint32_t l3 = cvt_tf32(x.w - __uint_as_float(h3));
            *(uint4*)&sm->Ah[r*RS + c4] = make_uint4(h0, h1, h2, h3);
            *(uint4*)&sm->Al[r*RS + c4] = make_uint4(l0, l1, l2, l3);
            float4 y = *(const float4*)&B[(size_t)(col0 + r) * DMODEL + k0 + c4];
            uint32_t j0 = cvt_tf32(y.x), j1 = cvt_tf32(y.y),
                     j2 = cvt_tf32(y.z), j3 = cvt_tf32(y.w);
            uint32_t m0 = cvt_tf32(y.x - __uint_as_float(j0));
            uint32_t m1 = cvt_tf32(y.y - __uint_as_float(j1));
            uint32_t m2 = cvt_tf32(y.z - __uint_as_float(j2));
            uint32_t m3 = cvt_tf32(y.w - __uint_as_float(j3));
            *(uint4*)&sm->Bh[r*RS + c4] = make_uint4(j0, j1, j2, j3);
            *(uint4*)&sm->Bl[r*RS + c4] = make_uint4(m0, m1, m2, m3);
        }
        __syncthreads();

#pragma unroll
        for (int ks = 0; ks < 2; ks++) {
            const int kk = ks * 8;
            uint32_t bh[4][2], bl[4][2];
#pragma unroll
            for (int nt = 0; nt < 4; nt++) {
                int nrow = cB + nt*8 + g;
                bh[nt][0] = sm->Bh[nrow*RS + kk + tig];
                bh[nt][1] = sm->Bh[nrow*RS + kk + tig + 4];
                bl[nt][0] = sm->Bl[nrow*RS + kk + tig];
                bl[nt][1] = sm->Bl[nrow*RS + kk + tig + 4];
            }
#pragma unroll
            for (int mt = 0; mt < 4; mt++) {
                int arow = rA + mt*16 + g;
                uint32_t ah[4], al[4];
                ah[0] = sm->Ah[arow*RS + kk + tig];
                ah[1] = sm->Ah[(arow+8)*RS + kk + tig];
                ah[2] = sm->Ah[arow*RS + kk + tig + 4];
                ah[3] = sm->Ah[(arow+8)*RS + kk + tig + 4];
                al[0] = sm->Al[arow*RS + kk + tig];
                al[1] = sm->Al[(arow+8)*RS + kk + tig];
                al[2] = sm->Al[arow*RS + kk + tig + 4];
                al[3] = sm->Al[(arow+8)*RS + kk + tig + 4];
#pragma unroll
                for (int nt = 0; nt < 4; nt++) {
                    mma8(acc[mt][nt], ah, bh[nt]);   // hi*hi
                    mma8(acc[mt][nt], ah, bl[nt]);   // hi*lo
                    mma8(acc[mt][nt], al, bh[nt]);   // lo*hi
                }
            }
        }
    }
}

// ============================================================================
// Fused QKV projections (grid.z selects which): out = X @ W^T + b, scattered
// to [B,H,S,dk] device scratch.
// ============================================================================
__global__ __launch_bounds__(256)
void k_projmma(const float* __restrict__ Qin, const float* __restrict__ Kin,
               const float* __restrict__ Vin,
               const float* __restrict__ Wq, const float* __restrict__ Wk,
               const float* __restrict__ Wv,
               const float* __restrict__ bq, const float* __restrict__ bk,
               const float* __restrict__ bv)
{
    __shared__ GemmSmem sm;
    const int z = blockIdx.z;
    const float* X = (z == 0) ? Qin : (z == 1) ? Kin : Vin;
    const float* W = (z == 0) ? Wq  : (z == 1) ? Wk  : Wv;
    const float* bias = (z == 0) ? bq : (z == 1) ? bk : bv;
    float* out = (z == 0) ? g_q : (z == 1) ? g_k : g_v;
    const int row0 = blockIdx.x * 128;
    const int col0 = blockIdx.y * 128;

    float acc[4][4][4];
    gemm_tf32x3(X, W, row0, col0, &sm, acc);

    const int tid = threadIdx.x;
    const int wid = tid >> 5, lane = tid & 31;
    const int g = lane >> 2, tig = lane & 3;
    const int warp_m = wid & 1, warp_n = wid >> 1;

#pragma unroll
    for (int nt = 0; nt < 4; nt++) {
        int col = col0 + warp_n*32 + nt*8 + tig*2;
        float b0 = bias[col], b1 = bias[col + 1];
        int h = col >> 6, dd = col & 63;
#pragma unroll
        for (int mt = 0; mt < 4; mt++) {
            int token = row0 + warp_m*64 + mt*16 + g;
            int b = token >> 11, s = token & (SEQ - 1);
            float* base = &out[(((size_t)(b*NHEADS + h))*SEQ + s)*DK + dd];
            *(float2*)base = make_float2(acc[mt][nt][0] + b0, acc[mt][nt][1] + b1);
            float* base2 = base + (size_t)8 * DK;   // token+8, same b (128-blk aligned)
            *(float2*)base2 = make_float2(acc[mt][nt][2] + b0, acc[mt][nt][3] + b1);
        }
    }
}

// ============================================================================
// Output GEMM: out = g_ctx @ Wo^T + bo + resid
// ============================================================================
__global__ __launch_bounds__(256)
void k_outmma(const float* __restrict__ W, const float* __restrict__ bias,
              const float* __restrict__ resid, float* __restrict__ out)
{
    __shared__ GemmSmem sm;
    const int row0 = blockIdx.x * 128;
    const int col0 = blockIdx.y * 128;

    float acc[4][4][4];
    gemm_tf32x3(g_ctx, W, row0, col0, &sm, acc);

    const int tid = threadIdx.x;
    const int wid = tid >> 5, lane = tid & 31;
    const int g = lane >> 2, tig = lane & 3;
    const int warp_m = wid & 1, warp_n = wid >> 1;

#pragma unroll
    for (int nt = 0; nt < 4; nt++) {
        int col = col0 + warp_n*32 + nt*8 + tig*2;
        float b0 = bias[col], b1 = bias[col + 1];
#pragma unroll
        for (int mt = 0; mt < 4; mt++) {
            int token = row0 + warp_m*64 + mt*16 + g;
            size_t gi = (size_t)token * DMODEL + col;
            float2 r0 = *(const float2*)&resid[gi];
            float2 r1 = *(const float2*)&resid[gi + 8*DMODEL];
            *(float2*)&out[gi] =
                make_float2(acc[mt][nt][0] + b0 + r0.x, acc[mt][nt][1] + b1 + r0.y);
            *(float2*)&out[gi + 8*DMODEL] =
                make_float2(acc[mt][nt][2] + b0 + r1.x, acc[mt][nt][3] + b1 + r1.y);
        }
    }
}

// ============================================================================
// Fused attention (validated round-2 version, FFMA)
// ============================================================================
#define SMEM_FLOATS (2*64*132 + 128*68)

__global__ __launch_bounds__(256, 2)
void k_attn(const unsigned char* __restrict__ mask,
            float* __restrict__ scores_g, float* __restrict__ attn_g)
{
    extern __shared__ float smf[];
    float* Qs = smf;
    float* Ks = smf + 64*132;
    float* Es = smf;
    float* Vs = smf + 2*64*132;

    const int tid = threadIdx.x;
    const int tx = tid & 15, ty = tid >> 4;
    const int qb = blockIdx.x, bh = blockIdx.y;
    const int b = bh >> 4, h = bh & 15;
    const int qr0 = qb * 128;
    const float* qp = g_q + (size_t)bh * SEQ * DK;
    const float* kp = g_k + (size_t)bh * SEQ * DK;
    const float* vp = g_v + (size_t)bh * SEQ * DK;
    float* srow = scores_g + ((size_t)bh * SEQ + qr0) * SEQ;
    float* arow = attn_g   + ((size_t)bh * SEQ + qr0) * SEQ;

#pragma unroll
    for (int l = 0; l < 8; l++) {
        int idx = tid + l * 256;
        int r = idx >> 4, c = (idx & 15) * 4;
        float4 qa = *(const float4*)&qp[(size_t)(qr0 + r) * DK + c];
        Qs[(c+0)*132 + r] = qa.x; Qs[(c+1)*132 + r] = qa.y;
        Qs[(c+2)*132 + r] = qa.z; Qs[(c+3)*132 + r] = qa.w;
    }

    float m[8], lsum[8];
#pragma unroll
    for (int i = 0; i < 8; i++) { m[i] = -3.0e38f; lsum[i] = 0.f; }

    for (int kt = 0; kt < 16; kt++) {
        __syncthreads();
#pragma unroll
        for (int l = 0; l < 8; l++) {
            int idx = tid + l * 256;
            int r = idx >> 4, c = (idx & 15) * 4;
            float4 ka = *(const float4*)&kp[(size_t)(kt*128 + r) * DK + c];
            Ks[(c+0)*132 + r] = ka.x; Ks[(c+1)*132 + r] = ka.y;
            Ks[(c+2)*132 + r] = ka.z; Ks[(c+3)*132 + r] = ka.w;
        }
        __syncthreads();

        float acc[8][8];
#pragma unroll
        for (int i = 0; i < 8; i++)
#pragma unroll
            for (int j = 0; j < 8; j++) acc[i][j] = 0.f;

#pragma unroll 16
        for (int kk = 0; kk < 64; kk++) {
            float4 a0 = *(const float4*)&Qs[kk*132 + ty*8];
            float4 a1 = *(const float4*)&Qs[kk*132 + ty*8 + 4];
            float4 b0 = *(const float4*)&Ks[kk*132 + tx*8];
            float4 b1 = *(const float4*)&Ks[kk*132 + tx*8 + 4];
            float a[8]  = {a0.x,a0.y,a0.z,a0.w,a1.x,a1.y,a1.z,a1.w};
            float bb[8] = {b0.x,b0.y,b0.z,b0.w,b1.x,b1.y,b1.z,b1.w};
#pragma unroll
            for (int i = 0; i < 8; i++)
#pragma unroll
                for (int j = 0; j < 8; j++) acc[i][j] += a[i] * bb[j];
        }

#pragma unroll
        for (int i = 0; i < 8; i++) {
            int qi = qr0 + ty*8 + i;
            const unsigned char* mrow =
                mask + ((size_t)b * SEQ + qi) * SEQ + kt*128 + tx*8;
            uint2 mk = *(const uint2*)mrow;
            float v[8];
#pragma unroll
            for (int j = 0; j < 8; j++) {
                unsigned byte = ((j < 4 ? mk.x >> (8*j) : mk.y >> (8*(j-4))) & 0xffu);
                v[j] = byte ? NEGVAL : acc[i][j] * 0.125f;
            }
            float* sp = &srow[(size_t)(ty*8 + i) * SEQ + kt*128 + tx*8];
            *(float4*)sp       = make_float4(v[0], v[1], v[2], v[3]);
            *(float4*)(sp + 4) = make_float4(v[4], v[5], v[6], v[7]);

            float tm = v[0];
#pragma unroll
            for (int j = 1; j < 8; j++) tm = fmaxf(tm, v[j]);
#pragma unroll
            for (int off = 1; off < 16; off <<= 1)
                tm = fmaxf(tm, __shfl_xor_sync(0xffffffffu, tm, off));
            float nm = fmaxf(m[i], tm);
            float ts = 0.f;
#pragma unroll
            for (int j = 0; j < 8; j++) ts += __expf(v[j] - nm);
#pragma unroll
            for (int off = 1; off < 16; off <<= 1)
                ts += __shfl_xor_sync(0xffffffffu, ts, off);
            lsum[i] = lsum[i] * __expf(m[i] - nm) + ts;
            m[i] = nm;
        }
    }

    float inv[8];
#pragma unroll
    for (int i = 0; i < 8; i++) inv[i] = 1.0f / lsum[i];

    float acc2[8][4];
#pragma unroll
    for (int i = 0; i < 8; i++)
#pragma unroll
        for (int j = 0; j < 4; j++) acc2[i][j] = 0.f;

    for (int kt = 15; kt >= 0; kt--) {
        __syncthreads();
#pragma unroll
        for (int l = 0; l < 8; l++) {
            int idx = tid + l * 256;
            int r = idx >> 4, c = (idx & 15) * 4;
            float4 va = *(const float4*)&vp[(size_t)(kt*128 + r) * DK + c];
            *(float4*)&Vs[r*68 + c] = va;
        }
#pragma unroll
        for (int ig = 0; ig < 2; ig++) {
            float er[4][8];
#pragma unroll
            for (int ii = 0; ii < 4; ii++) {
                int i = ig*4 + ii;
                const float* sp = &srow[(size_t)(ty*8 + i) * SEQ + kt*128 + tx*8];
                float4 s0 = *(const float4*)sp;
                float4 s1 = *(const float4*)(sp + 4);
                float mi = m[i], iv = inv[i];
                er[ii][0] = __expf(s0.x - mi) * iv;
                er[ii][1] = __expf(s0.y - mi) * iv;
                er[ii][2] = __expf(s0.z - mi) * iv;
                er[ii][3] = __expf(s0.w - mi) * iv;
                er[ii][4] = __expf(s1.x - mi) * iv;
                er[ii][5] = __expf(s1.y - mi) * iv;
                er[ii][6] = __expf(s1.z - mi) * iv;
                er[ii][7] = __expf(s1.w - mi) * iv;
                float* ap = &arow[(size_t)(ty*8 + i) * SEQ + kt*128 + tx*8];
                *(float4*)ap       = make_float4(er[ii][0], er[ii][1], er[ii][2], er[ii][3]);
                *(float4*)(ap + 4) = make_float4(er[ii][4], er[ii][5], er[ii][6], er[ii][7]);
            }
#pragma unroll
            for (int j = 0; j < 8; j++) {
                *(float4*)&Es[(tx*8 + j)*132 + ty*8 + ig*4] =
                    make_float4(er[0][j], er[1][j], er[2][j], er[3][j]);
            }
        }
        __syncthreads();

#pragma unroll 16
        for (int kk = 0; kk < 128; kk++) {
            float4 a0 = *(const float4*)&Es[kk*132 + ty*8];
            float4 a1 = *(const float4*)&Es[kk*132 + ty*8 + 4];
            float4 bv = *(const float4*)&Vs[kk*68 + tx*4];
            float a[8]  = {a0.x,a0.y,a0.z,a0.w,a1.x,a1.y,a1.z,a1.w};
            float bb[4] = {bv.x,bv.y,bv.z,bv.w};
#pragma unroll
            for (int i = 0; i < 8; i++)
#pragma unroll
                for (int j = 0; j < 4; j++) acc2[i][j] += a[i] * bb[j];
        }
    }

#pragma unroll
    for (int i = 0; i < 8; i++) {
        int s = qr0 + ty*8 + i;
        *(float4*)&g_ctx[((size_t)(b * SEQ + s)) * DMODEL + h*DK + tx*4] =
            make_float4(acc2[i][0], acc2[i][1], acc2[i][2], acc2[i][3]);
    }
}

// ============================================================================
extern "C" void kernel_launch(void* const* d_in, const int* in_sizes, int n_in,
                              void* d_out, int out_size)
{
    const float* Q  = (const float*)d_in[0];
    const float* K  = (const float*)d_in[1];
    const float* V  = (const float*)d_in[2];
    const unsigned char* mask = (const unsigned char*)d_in[3];
    const float* Wq = (const float*)d_in[4];  const float* bq = (const float*)d_in[5];
    const float* Wk = (const float*)d_in[6];  const float* bk = (const float*)d_in[7];
    const float* Wv = (const float*)d_in[8];  const float* bv = (const float*)d_in[9];
    const float* Wo = (const float*)d_in[10]; const float* bo = (const float*)d_in[11];

    float* out    = (float*)d_out;
    float* attn   = out + (size_t)NTOK * DMODEL;
    float* scores = attn + (size_t)BATCH * NHEADS * SEQ * SEQ;

    static const size_t attn_smem = SMEM_FLOATS * sizeof(float);
    cudaFuncSetAttribute(k_attn, cudaFuncAttributeMaxDynamicSharedMemorySize,
                         (int)attn_smem);

    dim3 gp(NTOK / 128, DMODEL / 128, 3);       // 32 x 8 x 3
    k_projmma<<<gp, 256>>>(Q, K, V, Wq, Wk, Wv, bq, bk, bv);

    dim3 gf(SEQ / 128, BATCH * NHEADS);         // 16 x 32
    k_attn<<<gf, 256, attn_smem>>>(mask, scores, attn);

    dim3 go(NTOK / 128, DMODEL / 128);          // 32 x 8
    k_outmma<<<go, 256>>>(Wo, bo, Q, out);
}

// round 5
// speedup vs baseline: 1.2158x; 1.0483x over previous
#include <cuda_runtime.h>
#include <cstdint>

#define BATCH 2
#define SEQ 2048
#define DMODEL 1024
#define NHEADS 16
#define DK 64
#define NTOK (BATCH*SEQ)          /* 4096 */
#define NEGVAL (-1000000000.0f)

// ---------------- scratch (device globals: allocation-free) ----------------
__device__ float g_q[(size_t)BATCH*NHEADS*SEQ*DK];   // 16 MB  [B,H,S,dk]
__device__ float g_k[(size_t)BATCH*NHEADS*SEQ*DK];   // 16 MB
__device__ float g_v[(size_t)BATCH*NHEADS*SEQ*DK];   // 16 MB
__device__ float g_ctx[(size_t)NTOK*DMODEL];         // 16 MB  [B,S,D]

// ============================ mma.sync helpers ==============================
__device__ __forceinline__ uint32_t cvt_tf32(float x) {
    uint32_t r; asm("cvt.rna.tf32.f32 %0, %1;" : "=r"(r) : "f"(x)); return r;
}
__device__ __forceinline__ void mma8(float* c, const uint32_t* a, const uint32_t* b) {
    asm volatile("mma.sync.aligned.m16n8k8.row.col.f32.tf32.tf32.f32 "
                 "{%0,%1,%2,%3}, {%4,%5,%6,%7}, {%8,%9}, {%0,%1,%2,%3};"
                 : "+f"(c[0]), "+f"(c[1]), "+f"(c[2]), "+f"(c[3])
                 : "r"(a[0]), "r"(a[1]), "r"(a[2]), "r"(a[3]),
                   "r"(b[0]), "r"(b[1]));
}

// ==================== tf32 3x GEMM core (HMMA path) =========================
#define RS 20
#define TILE_U32 (128*RS)

struct GemmSmem {
    uint32_t Ah[TILE_U32];
    uint32_t Al[TILE_U32];
    uint32_t Bh[TILE_U32];
    uint32_t Bl[TILE_U32];
};

__device__ __forceinline__ void gemm_tf32x3(
    const float* __restrict__ A, const float* __restrict__ B,
    int row0, int col0, GemmSmem* sm, float acc[4][4][4])
{
    const int tid = threadIdx.x;
    const int wid = tid >> 5, lane = tid & 31;
    const int g = lane >> 2, tig = lane & 3;
    const int warp_m = wid & 1;
    const int warp_n = wid >> 1;
    const int rA = warp_m * 64;
    const int cB = warp_n * 32;

#pragma unroll
    for (int mt = 0; mt < 4; mt++)
#pragma unroll
        for (int nt = 0; nt < 4; nt++)
#pragma unroll
            for (int q = 0; q < 4; q++) acc[mt][nt][q] = 0.f;

    for (int it = 0; it < DMODEL / 16; it++) {
        const int k0 = it * 16;
        __syncthreads();
#pragma unroll
        for (int l = 0; l < 2; l++) {
            int idx = tid + l * 256;
            int r = idx >> 2;
            int c4 = (idx & 3) * 4;
            float4 x = *(const float4*)&A[(size_t)(row0 + r) * DMODEL + k0 + c4];
            uint32_t h0 = cvt_tf32(x.x), h1 = cvt_tf32(x.y),
                     h2 = cvt_tf32(x.z), h3 = cvt_tf32(x.w);
            uint32_t l0 = cvt_tf32(x.x - __uint_as_float(h0));
            uint32_t l1 = cvt_tf32(x.y - __uint_as_float(h1));
            uint32_t l2 = cvt_tf32(x.z - __uint_as_float(h2));
            uint32_t l3 = cvt_tf32(x.w - __uint_as_float(h3));
            *(uint4*)&sm->Ah[r*RS + c4] = make_uint4(h0, h1, h2, h3);
            *(uint4*)&sm->Al[r*RS + c4] = make_uint4(l0, l1, l2, l3);
            float4 y = *(const float4*)&B[(size_t)(col0 + r) * DMODEL + k0 + c4];
            uint32_t j0 = cvt_tf32(y.x), j1 = cvt_tf32(y.y),
                     j2 = cvt_tf32(y.z), j3 = cvt_tf32(y.w);
            uint32_t m0 = cvt_tf32(y.x - __uint_as_float(j0));
            uint32_t m1 = cvt_tf32(y.y - __uint_as_float(j1));
            uint32_t m2 = cvt_tf32(y.z - __uint_as_float(j2));
            uint32_t m3 = cvt_tf32(y.w - __uint_as_float(j3));
            *(uint4*)&sm->Bh[r*RS + c4] = make_uint4(j0, j1, j2, j3);
            *(uint4*)&sm->Bl[r*RS + c4] = make_uint4(m0, m1, m2, m3);
        }
        __syncthreads();

#pragma unroll
        for (int ks = 0; ks < 2; ks++) {
            const int kk = ks * 8;
            uint32_t bh[4][2], bl[4][2];
#pragma unroll
            for (int nt = 0; nt < 4; nt++) {
                int nrow = cB + nt*8 + g;
                bh[nt][0] = sm->Bh[nrow*RS + kk + tig];
                bh[nt][1] = sm->Bh[nrow*RS + kk + tig + 4];
                bl[nt][0] = sm->Bl[nrow*RS + kk + tig];
                bl[nt][1] = sm->Bl[nrow*RS + kk + tig + 4];
            }
#pragma unroll
            for (int mt = 0; mt < 4; mt++) {
                int arow = rA + mt*16 + g;
                uint32_t ah[4], al[4];
                ah[0] = sm->Ah[arow*RS + kk + tig];
                ah[1] = sm->Ah[(arow+8)*RS + kk + tig];
                ah[2] = sm->Ah[arow*RS + kk + tig + 4];
                ah[3] = sm->Ah[(arow+8)*RS + kk + tig + 4];
                al[0] = sm->Al[arow*RS + kk + tig];
                al[1] = sm->Al[(arow+8)*RS + kk + tig];
                al[2] = sm->Al[arow*RS + kk + tig + 4];
                al[3] = sm->Al[(arow+8)*RS + kk + tig + 4];
#pragma unroll
                for (int nt = 0; nt < 4; nt++) {
                    mma8(acc[mt][nt], ah, bh[nt]);
                    mma8(acc[mt][nt], ah, bl[nt]);
                    mma8(acc[mt][nt], al, bh[nt]);
                }
            }
        }
    }
}

// ============================================================================
// Fused QKV projections
// ============================================================================
__global__ __launch_bounds__(256)
void k_projmma(const float* __restrict__ Qin, const float* __restrict__ Kin,
               const float* __restrict__ Vin,
               const float* __restrict__ Wq, const float* __restrict__ Wk,
               const float* __restrict__ Wv,
               const float* __restrict__ bq, const float* __restrict__ bk,
               const float* __restrict__ bv)
{
    __shared__ GemmSmem sm;
    const int z = blockIdx.z;
    const float* X = (z == 0) ? Qin : (z == 1) ? Kin : Vin;
    const float* W = (z == 0) ? Wq  : (z == 1) ? Wk  : Wv;
    const float* bias = (z == 0) ? bq : (z == 1) ? bk : bv;
    float* out = (z == 0) ? g_q : (z == 1) ? g_k : g_v;
    const int row0 = blockIdx.x * 128;
    const int col0 = blockIdx.y * 128;

    float acc[4][4][4];
    gemm_tf32x3(X, W, row0, col0, &sm, acc);

    const int tid = threadIdx.x;
    const int wid = tid >> 5, lane = tid & 31;
    const int g = lane >> 2, tig = lane & 3;
    const int warp_m = wid & 1, warp_n = wid >> 1;

#pragma unroll
    for (int nt = 0; nt < 4; nt++) {
        int col = col0 + warp_n*32 + nt*8 + tig*2;
        float b0 = bias[col], b1 = bias[col + 1];
        int h = col >> 6, dd = col & 63;
#pragma unroll
        for (int mt = 0; mt < 4; mt++) {
            int token = row0 + warp_m*64 + mt*16 + g;
            int b = token >> 11, s = token & (SEQ - 1);
            float* base = &out[(((size_t)(b*NHEADS + h))*SEQ + s)*DK + dd];
            *(float2*)base = make_float2(acc[mt][nt][0] + b0, acc[mt][nt][1] + b1);
            float* base2 = base + (size_t)8 * DK;
            *(float2*)base2 = make_float2(acc[mt][nt][2] + b0, acc[mt][nt][3] + b1);
        }
    }
}

// ============================================================================
// Output GEMM: out = g_ctx @ Wo^T + bo + resid
// ============================================================================
__global__ __launch_bounds__(256)
void k_outmma(const float* __restrict__ W, const float* __restrict__ bias,
              const float* __restrict__ resid, float* __restrict__ out)
{
    __shared__ GemmSmem sm;
    const int row0 = blockIdx.x * 128;
    const int col0 = blockIdx.y * 128;

    float acc[4][4][4];
    gemm_tf32x3(g_ctx, W, row0, col0, &sm, acc);

    const int tid = threadIdx.x;
    const int wid = tid >> 5, lane = tid & 31;
    const int g = lane >> 2, tig = lane & 3;
    const int warp_m = wid & 1, warp_n = wid >> 1;

#pragma unroll
    for (int nt = 0; nt < 4; nt++) {
        int col = col0 + warp_n*32 + nt*8 + tig*2;
        float b0 = bias[col], b1 = bias[col + 1];
#pragma unroll
        for (int mt = 0; mt < 4; mt++) {
            int token = row0 + warp_m*64 + mt*16 + g;
            size_t gi = (size_t)token * DMODEL + col;
            float2 r0 = *(const float2*)&resid[gi];
            float2 r1 = *(const float2*)&resid[gi + 8*DMODEL];
            *(float2*)&out[gi] =
                make_float2(acc[mt][nt][0] + b0 + r0.x, acc[mt][nt][1] + b1 + r0.y);
            *(float2*)&out[gi + 8*DMODEL] =
                make_float2(acc[mt][nt][2] + b0 + r1.x, acc[mt][nt][3] + b1 + r1.y);
        }
    }
}

// ============================================================================
// Fused attention on HMMA tf32x3.
// CTA = 128 q-rows x one (b,h). 8 warps, each warp owns 16 q-rows.
// Phase A: per 128-k tile: stage K hi/lo (stride 68), scores = Q@K^T via mma,
//          scale+mask+write scores, online row stats.
// Phase B: per 128-k tile (reverse): stage V hi/lo (stride 72), re-read scores
//          in A-frag layout, e = exp(s-m)/l, write attn, ctx += E@V via mma.
// ============================================================================
#define SA_HI 0
#define SA_LO 36864
#define SA_MK 73728
#define ATTN_SMEM (SA_MK + 16384)   /* 90112 bytes */

__global__ __launch_bounds__(256, 1)
void k_attn_mma(const unsigned char* __restrict__ mask,
                float* __restrict__ scores_g, float* __restrict__ attn_g)
{
    extern __shared__ char smc[];
    float* Sh = (float*)(smc + SA_HI);
    float* Sl = (float*)(smc + SA_LO);
    unsigned char* Mk = (unsigned char*)(smc + SA_MK);

    const int tid = threadIdx.x;
    const int wid = tid >> 5, lane = tid & 31;
    const int g = lane >> 2, tig = lane & 3;
    const int qb = blockIdx.x, bh = blockIdx.y;
    const int b = bh >> 4, h = bh & 15;
    const int qr0 = qb * 128;
    const float* qp = g_q + (size_t)bh * SEQ * DK;
    const float* kp = g_k + (size_t)bh * SEQ * DK;
    const float* vp = g_v + (size_t)bh * SEQ * DK;
    float* srow = scores_g + ((size_t)bh * SEQ + qr0) * SEQ;
    float* arow = attn_g   + ((size_t)bh * SEQ + qr0) * SEQ;

    // ---- stage Q raw into Sh[128][68]; load persistent A-fragments ----
#pragma unroll
    for (int l = 0; l < 8; l++) {
        int idx = tid + l * 256;            // 0..2047 float4s
        int r = idx >> 4, c4 = (idx & 15) * 4;
        float4 q = *(const float4*)&qp[(size_t)(qr0 + r) * DK + c4];
        *(float4*)&Sh[r*68 + c4] = q;
    }
    __syncthreads();
    uint32_t aQh[8][4], aQl[8][4];
    {
        const int r0 = wid*16 + g, r1 = r0 + 8;
#pragma unroll
        for (int ks = 0; ks < 8; ks++) {
            float q0 = Sh[r0*68 + ks*8 + tig];
            float q1 = Sh[r1*68 + ks*8 + tig];
            float q2 = Sh[r0*68 + ks*8 + tig + 4];
            float q3 = Sh[r1*68 + ks*8 + tig + 4];
            aQh[ks][0] = cvt_tf32(q0); aQl[ks][0] = cvt_tf32(q0 - __uint_as_float(aQh[ks][0]));
            aQh[ks][1] = cvt_tf32(q1); aQl[ks][1] = cvt_tf32(q1 - __uint_as_float(aQh[ks][1]));
            aQh[ks][2] = cvt_tf32(q2); aQl[ks][2] = cvt_tf32(q2 - __uint_as_float(aQh[ks][2]));
            aQh[ks][3] = cvt_tf32(q3); aQl[ks][3] = cvt_tf32(q3 - __uint_as_float(aQh[ks][3]));
        }
    }

    float mrow[2] = {-3.0e38f, -3.0e38f};
    float lrow[2] = {0.f, 0.f};

    // ======================= PASS A: scores + stats =======================
    for (int kt = 0; kt < 16; kt++) {
        __syncthreads();
        // stage K tile hi/lo, stride 68
#pragma unroll
        for (int l = 0; l < 8; l++) {
            int idx = tid + l * 256;
            int r = idx >> 4, c4 = (idx & 15) * 4;
            float4 x = *(const float4*)&kp[(size_t)(kt*128 + r) * DK + c4];
            uint32_t h0 = cvt_tf32(x.x), h1 = cvt_tf32(x.y),
                     h2 = cvt_tf32(x.z), h3 = cvt_tf32(x.w);
            float4 lo = make_float4(
                __uint_as_float(cvt_tf32(x.x - __uint_as_float(h0))),
                __uint_as_float(cvt_tf32(x.y - __uint_as_float(h1))),
                __uint_as_float(cvt_tf32(x.z - __uint_as_float(h2))),
                __uint_as_float(cvt_tf32(x.w - __uint_as_float(h3))));
            *(float4*)&Sh[r*68 + c4] = make_float4(
                __uint_as_float(h0), __uint_as_float(h1),
                __uint_as_float(h2), __uint_as_float(h3));
            *(float4*)&Sl[r*68 + c4] = lo;
        }
        // stage mask tile [128][128] bytes
#pragma unroll
        for (int l = 0; l < 4; l++) {
            int idx = tid + l * 256;
            int r = idx >> 3, c16 = (idx & 7) * 16;
            *(uint4*)&Mk[r*128 + c16] =
                *(const uint4*)&mask[((size_t)b*SEQ + qr0 + r)*SEQ + kt*128 + c16];
        }
        __syncthreads();

        float acc[16][4];
#pragma unroll
        for (int nt = 0; nt < 16; nt++)
#pragma unroll
            for (int q = 0; q < 4; q++) acc[nt][q] = 0.f;

#pragma unroll
        for (int nt = 0; nt < 16; nt++) {
            const int nr = nt*8 + g;
#pragma unroll
            for (int ks = 0; ks < 8; ks++) {
                uint32_t bhv[2], blv[2];
                bhv[0] = __float_as_uint(Sh[nr*68 + ks*8 + tig]);
                bhv[1] = __float_as_uint(Sh[nr*68 + ks*8 + tig + 4]);
                blv[0] = __float_as_uint(Sl[nr*68 + ks*8 + tig]);
                blv[1] = __float_as_uint(Sl[nr*68 + ks*8 + tig + 4]);
                mma8(acc[nt], aQh[ks], bhv);
                mma8(acc[nt], aQh[ks], blv);
                mma8(acc[nt], aQl[ks], bhv);
            }
        }

        // epilogue: scale + mask + stats + store
        const int r0 = wid*16 + g, r1 = r0 + 8;
        float mn0 = mrow[0], mn1 = mrow[1];
#pragma unroll
        for (int nt = 0; nt < 16; nt++) {
            int c = nt*8 + tig*2;
            acc[nt][0] = Mk[r0*128 + c]     ? NEGVAL : acc[nt][0] * 0.125f;
            acc[nt][1] = Mk[r0*128 + c + 1] ? NEGVAL : acc[nt][1] * 0.125f;
            acc[nt][2] = Mk[r1*128 + c]     ? NEGVAL : acc[nt][2] * 0.125f;
            acc[nt][3] = Mk[r1*128 + c + 1] ? NEGVAL : acc[nt][3] * 0.125f;
            mn0 = fmaxf(mn0, fmaxf(acc[nt][0], acc[nt][1]));
            mn1 = fmaxf(mn1, fmaxf(acc[nt][2], acc[nt][3]));
        }
        mn0 = fmaxf(mn0, __shfl_xor_sync(0xffffffffu, mn0, 1));
        mn0 = fmaxf(mn0, __shfl_xor_sync(0xffffffffu, mn0, 2));
        mn1 = fmaxf(mn1, __shfl_xor_sync(0xffffffffu, mn1, 1));
        mn1 = fmaxf(mn1, __shfl_xor_sync(0xffffffffu, mn1, 2));
        float ts0 = 0.f, ts1 = 0.f;
#pragma unroll
        for (int nt = 0; nt < 16; nt++) {
            ts0 += __expf(acc[nt][0] - mn0) + __expf(acc[nt][1] - mn0);
            ts1 += __expf(acc[nt][2] - mn1) + __expf(acc[nt][3] - mn1);
        }
        ts0 += __shfl_xor_sync(0xffffffffu, ts0, 1);
        ts0 += __shfl_xor_sync(0xffffffffu, ts0, 2);
        ts1 += __shfl_xor_sync(0xffffffffu, ts1, 1);
        ts1 += __shfl_xor_sync(0xffffffffu, ts1, 2);
        lrow[0] = lrow[0] * __expf(mrow[0] - mn0) + ts0;  mrow[0] = mn0;
        lrow[1] = lrow[1] * __expf(mrow[1] - mn1) + ts1;  mrow[1] = mn1;
#pragma unroll
        for (int nt = 0; nt < 16; nt++) {
            int c = kt*128 + nt*8 + tig*2;
            *(float2*)&srow[(size_t)r0 * SEQ + c] = make_float2(acc[nt][0], acc[nt][1]);
            *(float2*)&srow[(size_t)r1 * SEQ + c] = make_float2(acc[nt][2], acc[nt][3]);
        }
    }

    const float inv0 = 1.0f / lrow[0];
    const float inv1 = 1.0f / lrow[1];

    // ======================= PASS B: attn + E@V ===========================
    float co[8][4];
#pragma unroll
    for (int nt = 0; nt < 8; nt++)
#pragma unroll
        for (int q = 0; q < 4; q++) co[nt][q] = 0.f;

    const int r0 = wid*16 + g, r1 = r0 + 8;
    for (int kt = 15; kt >= 0; kt--) {
        __syncthreads();
        // stage V tile hi/lo, natural [krow][d], stride 72
#pragma unroll
        for (int l = 0; l < 8; l++) {
            int idx = tid + l * 256;
            int r = idx >> 4, c4 = (idx & 15) * 4;
            float4 x = *(const float4*)&vp[(size_t)(kt*128 + r) * DK + c4];
            uint32_t h0 = cvt_tf32(x.x), h1 = cvt_tf32(x.y),
                     h2 = cvt_tf32(x.z), h3 = cvt_tf32(x.w);
            float4 lo = make_float4(
                __uint_as_float(cvt_tf32(x.x - __uint_as_float(h0))),
                __uint_as_float(cvt_tf32(x.y - __uint_as_float(h1))),
                __uint_as_float(cvt_tf32(x.z - __uint_as_float(h2))),
                __uint_as_float(cvt_tf32(x.w - __uint_as_float(h3))));
            *(float4*)&Sh[r*72 + c4] = make_float4(
                __uint_as_float(h0), __uint_as_float(h1),
                __uint_as_float(h2), __uint_as_float(h3));
            *(float4*)&Sl[r*72 + c4] = lo;
        }
        __syncthreads();

#pragma unroll
        for (int ks = 0; ks < 16; ks++) {
            const size_t c0 = (size_t)kt*128 + ks*8 + tig;
            float s0 = srow[(size_t)r0 * SEQ + c0];
            float s1 = srow[(size_t)r1 * SEQ + c0];
            float s2 = srow[(size_t)r0 * SEQ + c0 + 4];
            float s3 = srow[(size_t)r1 * SEQ + c0 + 4];
            float e0 = __expf(s0 - mrow[0]) * inv0;
            float e1 = __expf(s1 - mrow[1]) * inv1;
            float e2 = __expf(s2 - mrow[0]) * inv0;
            float e3 = __expf(s3 - mrow[1]) * inv1;
            arow[(size_t)r0 * SEQ + c0]     = e0;
            arow[(size_t)r1 * SEQ + c0]     = e1;
            arow[(size_t)r0 * SEQ + c0 + 4] = e2;
            arow[(size_t)r1 * SEQ + c0 + 4] = e3;
            uint32_t aeh[4], ael[4];
            aeh[0] = cvt_tf32(e0); ael[0] = cvt_tf32(e0 - __uint_as_float(aeh[0]));
            aeh[1] = cvt_tf32(e1); ael[1] = cvt_tf32(e1 - __uint_as_float(aeh[1]));
            aeh[2] = cvt_tf32(e2); ael[2] = cvt_tf32(e2 - __uint_as_float(aeh[2]));
            aeh[3] = cvt_tf32(e3); ael[3] = cvt_tf32(e3 - __uint_as_float(aeh[3]));
#pragma unroll
            for (int nt = 0; nt < 8; nt++) {
                uint32_t bhv[2], blv[2];
                bhv[0] = __float_as_uint(Sh[(ks*8 + tig)*72 + nt*8 + g]);
                bhv[1] = __float_as_uint(Sh[(ks*8 + tig + 4)*72 + nt*8 + g]);
                blv[0] = __float_as_uint(Sl[(ks*8 + tig)*72 + nt*8 + g]);
                blv[1] = __float_as_uint(Sl[(ks*8 + tig + 4)*72 + nt*8 + g]);
                mma8(co[nt], aeh, bhv);
                mma8(co[nt], aeh, blv);
                mma8(co[nt], ael, bhv);
            }
        }
    }

    // write ctx [B,S,D]
#pragma unroll
    for (int nt = 0; nt < 8; nt++) {
        int d = nt*8 + tig*2;
        *(float2*)&g_ctx[((size_t)(b*SEQ) + qr0 + r0) * DMODEL + h*DK + d] =
            make_float2(co[nt][0], co[nt][1]);
        *(float2*)&g_ctx[((size_t)(b*SEQ) + qr0 + r1) * DMODEL + h*DK + d] =
            make_float2(co[nt][2], co[nt][3]);
    }
}

// ============================================================================
extern "C" void kernel_launch(void* const* d_in, const int* in_sizes, int n_in,
                              void* d_out, int out_size)
{
    const float* Q  = (const float*)d_in[0];
    const float* K  = (const float*)d_in[1];
    const float* V  = (const float*)d_in[2];
    const unsigned char* mask = (const unsigned char*)d_in[3];
    const float* Wq = (const float*)d_in[4];  const float* bq = (const float*)d_in[5];
    const float* Wk = (const float*)d_in[6];  const float* bk = (const float*)d_in[7];
    const float* Wv = (const float*)d_in[8];  const float* bv = (const float*)d_in[9];
    const float* Wo = (const float*)d_in[10]; const float* bo = (const float*)d_in[11];

    float* out    = (float*)d_out;
    float* attn   = out + (size_t)NTOK * DMODEL;
    float* scores = attn + (size_t)BATCH * NHEADS * SEQ * SEQ;

    cudaFuncSetAttribute(k_attn_mma, cudaFuncAttributeMaxDynamicSharedMemorySize,
                         ATTN_SMEM);

    dim3 gp(NTOK / 128, DMODEL / 128, 3);       // 32 x 8 x 3
    k_projmma<<<gp, 256>>>(Q, K, V, Wq, Wk, Wv, bq, bk, bv);

    dim3 gf(SEQ / 128, BATCH * NHEADS);         // 16 x 32
    k_attn_mma<<<gf, 256, ATTN_SMEM>>>(mask, scores, attn);

    dim3 go(NTOK / 128, DMODEL / 128);          // 32 x 8
    k_outmma<<<go, 256>>>(Wo, bo, Q, out);
}

// round 7
// speedup vs baseline: 1.3718x; 1.1284x over previous
#include <cuda_runtime.h>
#include <cstdint>

#define BATCH 2
#define SEQ 2048
#define DMODEL 1024
#define NHEADS 16
#define DK 64
#define NTOK (BATCH*SEQ)          /* 4096 */
#define NEGVAL (-1000000000.0f)

// ---------------- scratch (device globals: allocation-free) ----------------
__device__ float g_q[(size_t)BATCH*NHEADS*SEQ*DK];   // 16 MB  [B,H,S,dk]
__device__ float g_k[(size_t)BATCH*NHEADS*SEQ*DK];   // 16 MB
__device__ float g_v[(size_t)BATCH*NHEADS*SEQ*DK];   // 16 MB
__device__ float g_ctx[(size_t)NTOK*DMODEL];         // 16 MB  [B,S,D]

// ============================ mma.sync helpers ==============================
__device__ __forceinline__ uint32_t cvt_tf32(float x) {
    uint32_t r; asm("cvt.rna.tf32.f32 %0, %1;" : "=r"(r) : "f"(x)); return r;
}
__device__ __forceinline__ void mma8(float* c, const uint32_t* a, const uint32_t* b) {
    asm volatile("mma.sync.aligned.m16n8k8.row.col.f32.tf32.tf32.f32 "
                 "{%0,%1,%2,%3}, {%4,%5,%6,%7}, {%8,%9}, {%0,%1,%2,%3};"
                 : "+f"(c[0]), "+f"(c[1]), "+f"(c[2]), "+f"(c[3])
                 : "r"(a[0]), "r"(a[1]), "r"(a[2]), "r"(a[3]),
                   "r"(b[0]), "r"(b[1]));
}

// ==================== tf32 3x GEMM core (HMMA path) =========================
#define RS 20
#define TILE_U32 (128*RS)

struct GemmSmem {
    uint32_t Ah[TILE_U32];
    uint32_t Al[TILE_U32];
    uint32_t Bh[TILE_U32];
    uint32_t Bl[TILE_U32];
};

__device__ __forceinline__ void gemm_tf32x3(
    const float* __restrict__ A, const float* __restrict__ B,
    int row0, int col0, GemmSmem* sm, float acc[4][4][4])
{
    const int tid = threadIdx.x;
    const int wid = tid >> 5, lane = tid & 31;
    const int g = lane >> 2, tig = lane & 3;
    const int warp_m = wid & 1;
    const int warp_n = wid >> 1;
    const int rA = warp_m * 64;
    const int cB = warp_n * 32;

#pragma unroll
    for (int mt = 0; mt < 4; mt++)
#pragma unroll
        for (int nt = 0; nt < 4; nt++)
#pragma unroll
            for (int q = 0; q < 4; q++) acc[mt][nt][q] = 0.f;

    for (int it = 0; it < DMODEL / 16; it++) {
        const int k0 = it * 16;
        __syncthreads();
#pragma unroll
        for (int l = 0; l < 2; l++) {
            int idx = tid + l * 256;
            int r = idx >> 2;
            int c4 = (idx & 3) * 4;
            float4 x = *(const float4*)&A[(size_t)(row0 + r) * DMODEL + k0 + c4];
            uint32_t h0 = cvt_tf32(x.x), h1 = cvt_tf32(x.y),
                     h2 = cvt_tf32(x.z), h3 = cvt_tf32(x.w);
            uint32_t l0 = cvt_tf32(x.x - __uint_as_float(h0));
            uint32_t l1 = cvt_tf32(x.y - __uint_as_float(h1));
            uint32_t l2 = cvt_tf32(x.z - __uint_as_float(h2));
            uint32_t l3 = cvt_tf32(x.w - __uint_as_float(h3));
            *(uint4*)&sm->Ah[r*RS + c4] = make_uint4(h0, h1, h2, h3);
            *(uint4*)&sm->Al[r*RS + c4] = make_uint4(l0, l1, l2, l3);
            float4 y = *(const float4*)&B[(size_t)(col0 + r) * DMODEL + k0 + c4];
            uint32_t j0 = cvt_tf32(y.x), j1 = cvt_tf32(y.y),
                     j2 = cvt_tf32(y.z), j3 = cvt_tf32(y.w);
            uint32_t m0 = cvt_tf32(y.x - __uint_as_float(j0));
            uint32_t m1 = cvt_tf32(y.y - __uint_as_float(j1));
            uint32_t m2 = cvt_tf32(y.z - __uint_as_float(j2));
            uint32_t m3 = cvt_tf32(y.w - __uint_as_float(j3));
            *(uint4*)&sm->Bh[r*RS + c4] = make_uint4(j0, j1, j2, j3);
            *(uint4*)&sm->Bl[r*RS + c4] = make_uint4(m0, m1, m2, m3);
        }
        __syncthreads();

#pragma unroll
        for (int ks = 0; ks < 2; ks++) {
            const int kk = ks * 8;
            uint32_t bh[4][2], bl[4][2];
#pragma unroll
            for (int nt = 0; nt < 4; nt++) {
                int nrow = cB + nt*8 + g;
                bh[nt][0] = sm->Bh[nrow*RS + kk + tig];
                bh[nt][1] = sm->Bh[nrow*RS + kk + tig + 4];
                bl[nt][0] = sm->Bl[nrow*RS + kk + tig];
                bl[nt][1] = sm->Bl[nrow*RS + kk + tig + 4];
            }
#pragma unroll
            for (int mt = 0; mt < 4; mt++) {
                int arow = rA + mt*16 + g;
                uint32_t ah[4], al[4];
                ah[0] = sm->Ah[arow*RS + kk + tig];
                ah[1] = sm->Ah[(arow+8)*RS + kk + tig];
                ah[2] = sm->Ah[arow*RS + kk + tig + 4];
                ah[3] = sm->Ah[(arow+8)*RS + kk + tig + 4];
                al[0] = sm->Al[arow*RS + kk + tig];
                al[1] = sm->Al[(arow+8)*RS + kk + tig];
                al[2] = sm->Al[arow*RS + kk + tig + 4];
                al[3] = sm->Al[(arow+8)*RS + kk + tig + 4];
#pragma unroll
                for (int nt = 0; nt < 4; nt++) {
                    mma8(acc[mt][nt], ah, bh[nt]);
                    mma8(acc[mt][nt], ah, bl[nt]);
                    mma8(acc[mt][nt], al, bh[nt]);
                }
            }
        }
    }
}

// ============================================================================
// Fused QKV projections
// ============================================================================
__global__ __launch_bounds__(256, 2)
void k_projmma(const float* __restrict__ Qin, const float* __restrict__ Kin,
               const float* __restrict__ Vin,
               const float* __restrict__ Wq, const float* __restrict__ Wk,
               const float* __restrict__ Wv,
               const float* __restrict__ bq, const float* __restrict__ bk,
               const float* __restrict__ bv)
{
    __shared__ GemmSmem sm;
    const int z = blockIdx.z;
    const float* X = (z == 0) ? Qin : (z == 1) ? Kin : Vin;
    const float* W = (z == 0) ? Wq  : (z == 1) ? Wk  : Wv;
    const float* bias = (z == 0) ? bq : (z == 1) ? bk : bv;
    float* out = (z == 0) ? g_q : (z == 1) ? g_k : g_v;
    const int row0 = blockIdx.x * 128;
    const int col0 = blockIdx.y * 128;

    float acc[4][4][4];
    gemm_tf32x3(X, W, row0, col0, &sm, acc);

    const int tid = threadIdx.x;
    const int wid = tid >> 5, lane = tid & 31;
    const int g = lane >> 2, tig = lane & 3;
    const int warp_m = wid & 1, warp_n = wid >> 1;

#pragma unroll
    for (int nt = 0; nt < 4; nt++) {
        int col = col0 + warp_n*32 + nt*8 + tig*2;
        float b0 = bias[col], b1 = bias[col + 1];
        int h = col >> 6, dd = col & 63;
#pragma unroll
        for (int mt = 0; mt < 4; mt++) {
            int token = row0 + warp_m*64 + mt*16 + g;
            int b = token >> 11, s = token & (SEQ - 1);
            float* base = &out[(((size_t)(b*NHEADS + h))*SEQ + s)*DK + dd];
            *(float2*)base = make_float2(acc[mt][nt][0] + b0, acc[mt][nt][1] + b1);
            float* base2 = base + (size_t)8 * DK;
            *(float2*)base2 = make_float2(acc[mt][nt][2] + b0, acc[mt][nt][3] + b1);
        }
    }
}

// ============================================================================
// Output GEMM: out = g_ctx @ Wo^T + bo + resid
// ============================================================================
__global__ __launch_bounds__(256, 2)
void k_outmma(const float* __restrict__ W, const float* __restrict__ bias,
              const float* __restrict__ resid, float* __restrict__ out)
{
    __shared__ GemmSmem sm;
    const int row0 = blockIdx.x * 128;
    const int col0 = blockIdx.y * 128;

    float acc[4][4][4];
    gemm_tf32x3(g_ctx, W, row0, col0, &sm, acc);

    const int tid = threadIdx.x;
    const int wid = tid >> 5, lane = tid & 31;
    const int g = lane >> 2, tig = lane & 3;
    const int warp_m = wid & 1, warp_n = wid >> 1;

#pragma unroll
    for (int nt = 0; nt < 4; nt++) {
        int col = col0 + warp_n*32 + nt*8 + tig*2;
        float b0 = bias[col], b1 = bias[col + 1];
#pragma unroll
        for (int mt = 0; mt < 4; mt++) {
            int token = row0 + warp_m*64 + mt*16 + g;
            size_t gi = (size_t)token * DMODEL + col;
            float2 r0 = *(const float2*)&resid[gi];
            float2 r1 = *(const float2*)&resid[gi + 8*DMODEL];
            *(float2*)&out[gi] =
                make_float2(acc[mt][nt][0] + b0 + r0.x, acc[mt][nt][1] + b1 + r0.y);
            *(float2*)&out[gi + 8*DMODEL] =
                make_float2(acc[mt][nt][2] + b0 + r1.x, acc[mt][nt][3] + b1 + r1.y);
        }
    }
}

// ============================================================================
// Fused attention on HMMA tf32x3, 64-row k-tiles for 2-CTA/SM occupancy.
// CTA = 128 q-rows x one (b,h). 8 warps, each warp owns 16 q-rows.
// smem layout (fixed round-6 overlap): hi region sized for max stride 72.
// ============================================================================
#define KTILE 64
#define NKT (SEQ/KTILE)            /* 32 */
#define SA_LO_OFF 18432            /* 64 rows x stride<=72 x 4B */
#define SA_MK_OFF 36864
#define ATTN_SMEM (SA_MK_OFF + 128*KTILE)   /* 45056 bytes */

__global__ __launch_bounds__(256, 2)
void k_attn_mma(const unsigned char* __restrict__ mask,
                float* __restrict__ scores_g, float* __restrict__ attn_g)
{
    extern __shared__ char smc[];
    float* Sh = (float*)smc;                       // K/V hi (64 x stride)
    float* Sl = (float*)(smc + SA_LO_OFF);         // K/V lo
    unsigned char* Mk = (unsigned char*)(smc + SA_MK_OFF);  // mask 128x64

    const int tid = threadIdx.x;
    const int wid = tid >> 5, lane = tid & 31;
    const int g = lane >> 2, tig = lane & 3;
    const int qb = blockIdx.x, bh = blockIdx.y;
    const int b = bh >> 4, h = bh & 15;
    const int qr0 = qb * 128;
    const float* qp = g_q + (size_t)bh * SEQ * DK;
    const float* kp = g_k + (size_t)bh * SEQ * DK;
    const float* vp = g_v + (size_t)bh * SEQ * DK;
    float* srow = scores_g + ((size_t)bh * SEQ + qr0) * SEQ;
    float* arow = attn_g   + ((size_t)bh * SEQ + qr0) * SEQ;

    // ---- stage Q raw (128x68, fits below mask region); persistent A-frags --
#pragma unroll
    for (int l = 0; l < 8; l++) {
        int idx = tid + l * 256;
        int r = idx >> 4, c4 = (idx & 15) * 4;
        float4 q = *(const float4*)&qp[(size_t)(qr0 + r) * DK + c4];
        *(float4*)&Sh[r*68 + c4] = q;
    }
    __syncthreads();
    uint32_t aQh[8][4], aQl[8][4];
    {
        const int r0q = wid*16 + g, r1q = r0q + 8;
#pragma unroll
        for (int ks = 0; ks < 8; ks++) {
            float q0 = Sh[r0q*68 + ks*8 + tig];
            float q1 = Sh[r1q*68 + ks*8 + tig];
            float q2 = Sh[r0q*68 + ks*8 + tig + 4];
            float q3 = Sh[r1q*68 + ks*8 + tig + 4];
            aQh[ks][0] = cvt_tf32(q0); aQl[ks][0] = cvt_tf32(q0 - __uint_as_float(aQh[ks][0]));
            aQh[ks][1] = cvt_tf32(q1); aQl[ks][1] = cvt_tf32(q1 - __uint_as_float(aQh[ks][1]));
            aQh[ks][2] = cvt_tf32(q2); aQl[ks][2] = cvt_tf32(q2 - __uint_as_float(aQh[ks][2]));
            aQh[ks][3] = cvt_tf32(q3); aQl[ks][3] = cvt_tf32(q3 - __uint_as_float(aQh[ks][3]));
        }
    }

    float mrow[2] = {-3.0e38f, -3.0e38f};
    float lrow[2] = {0.f, 0.f};
    const int r0 = wid*16 + g, r1 = r0 + 8;

    // ======================= PASS A: scores + stats =======================
    for (int kt = 0; kt < NKT; kt++) {
        __syncthreads();
        // stage K tile (64 x 64) hi/lo, stride 68
#pragma unroll
        for (int l = 0; l < 4; l++) {
            int idx = tid + l * 256;             // 0..1023
            int r = idx >> 4, c4 = (idx & 15) * 4;
            float4 x = *(const float4*)&kp[(size_t)(kt*KTILE + r) * DK + c4];
            uint32_t h0 = cvt_tf32(x.x), h1 = cvt_tf32(x.y),
                     h2 = cvt_tf32(x.z), h3 = cvt_tf32(x.w);
            float4 lo = make_float4(
                __uint_as_float(cvt_tf32(x.x - __uint_as_float(h0))),
                __uint_as_float(cvt_tf32(x.y - __uint_as_float(h1))),
                __uint_as_float(cvt_tf32(x.z - __uint_as_float(h2))),
                __uint_as_float(cvt_tf32(x.w - __uint_as_float(h3))));
            *(float4*)&Sh[r*68 + c4] = make_float4(
                __uint_as_float(h0), __uint_as_float(h1),
                __uint_as_float(h2), __uint_as_float(h3));
            *(float4*)&Sl[r*68 + c4] = lo;
        }
        // stage mask tile [128][64] bytes
#pragma unroll
        for (int l = 0; l < 2; l++) {
            int idx = tid + l * 256;             // 0..511
            int r = idx >> 2, c16 = (idx & 3) * 16;
            *(uint4*)&Mk[r*KTILE + c16] =
                *(const uint4*)&mask[((size_t)b*SEQ + qr0 + r)*SEQ + kt*KTILE + c16];
        }
        __syncthreads();

        float acc[8][4];
#pragma unroll
        for (int nt = 0; nt < 8; nt++)
#pragma unroll
            for (int q = 0; q < 4; q++) acc[nt][q] = 0.f;

#pragma unroll
        for (int nt = 0; nt < 8; nt++) {
            const int nr = nt*8 + g;
#pragma unroll
            for (int ks = 0; ks < 8; ks++) {
                uint32_t bhv[2], blv[2];
                bhv[0] = __float_as_uint(Sh[nr*68 + ks*8 + tig]);
                bhv[1] = __float_as_uint(Sh[nr*68 + ks*8 + tig + 4]);
                blv[0] = __float_as_uint(Sl[nr*68 + ks*8 + tig]);
                blv[1] = __float_as_uint(Sl[nr*68 + ks*8 + tig + 4]);
                mma8(acc[nt], aQh[ks], bhv);
                mma8(acc[nt], aQh[ks], blv);
                mma8(acc[nt], aQl[ks], bhv);
            }
        }

        // epilogue: scale + mask + stats + store
        float mn0 = mrow[0], mn1 = mrow[1];
#pragma unroll
        for (int nt = 0; nt < 8; nt++) {
            int c = nt*8 + tig*2;
            acc[nt][0] = Mk[r0*KTILE + c]     ? NEGVAL : acc[nt][0] * 0.125f;
            acc[nt][1] = Mk[r0*KTILE + c + 1] ? NEGVAL : acc[nt][1] * 0.125f;
            acc[nt][2] = Mk[r1*KTILE + c]     ? NEGVAL : acc[nt][2] * 0.125f;
            acc[nt][3] = Mk[r1*KTILE + c + 1] ? NEGVAL : acc[nt][3] * 0.125f;
            mn0 = fmaxf(mn0, fmaxf(acc[nt][0], acc[nt][1]));
            mn1 = fmaxf(mn1, fmaxf(acc[nt][2], acc[nt][3]));
        }
        mn0 = fmaxf(mn0, __shfl_xor_sync(0xffffffffu, mn0, 1));
        mn0 = fmaxf(mn0, __shfl_xor_sync(0xffffffffu, mn0, 2));
        mn1 = fmaxf(mn1, __shfl_xor_sync(0xffffffffu, mn1, 1));
        mn1 = fmaxf(mn1, __shfl_xor_sync(0xffffffffu, mn1, 2));
        float ts0 = 0.f, ts1 = 0.f;
#pragma unroll
        for (int nt = 0; nt < 8; nt++) {
            ts0 += __expf(acc[nt][0] - mn0) + __expf(acc[nt][1] - mn0);
            ts1 += __expf(acc[nt][2] - mn1) + __expf(acc[nt][3] - mn1);
        }
        ts0 += __shfl_xor_sync(0xffffffffu, ts0, 1);
        ts0 += __shfl_xor_sync(0xffffffffu, ts0, 2);
        ts1 += __shfl_xor_sync(0xffffffffu, ts1, 1);
        ts1 += __shfl_xor_sync(0xffffffffu, ts1, 2);
        lrow[0] = lrow[0] * __expf(mrow[0] - mn0) + ts0;  mrow[0] = mn0;
        lrow[1] = lrow[1] * __expf(mrow[1] - mn1) + ts1;  mrow[1] = mn1;
#pragma unroll
        for (int nt = 0; nt < 8; nt++) {
            int c = kt*KTILE + nt*8 + tig*2;
            *(float2*)&srow[(size_t)r0 * SEQ + c] = make_float2(acc[nt][0], acc[nt][1]);
            *(float2*)&srow[(size_t)r1 * SEQ + c] = make_float2(acc[nt][2], acc[nt][3]);
        }
    }

    const float inv0 = 1.0f / lrow[0];
    const float inv1 = 1.0f / lrow[1];

    // ======================= PASS B: attn + E@V ===========================
    float co[8][4];
#pragma unroll
    for (int nt = 0; nt < 8; nt++)
#pragma unroll
        for (int q = 0; q < 4; q++) co[nt][q] = 0.f;

    for (int kt = NKT - 1; kt >= 0; kt--) {
        __syncthreads();
        // stage V tile (64 x 64) hi/lo, natural [krow][d], stride 72
#pragma unroll
        for (int l = 0; l < 4; l++) {
            int idx = tid + l * 256;
            int r = idx >> 4, c4 = (idx & 15) * 4;
            float4 x = *(const float4*)&vp[(size_t)(kt*KTILE + r) * DK + c4];
            uint32_t h0 = cvt_tf32(x.x), h1 = cvt_tf32(x.y),
                     h2 = cvt_tf32(x.z), h3 = cvt_tf32(x.w);
            float4 lo = make_float4(
                __uint_as_float(cvt_tf32(x.x - __uint_as_float(h0))),
                __uint_as_float(cvt_tf32(x.y - __uint_as_float(h1))),
                __uint_as_float(cvt_tf32(x.z - __uint_as_float(h2))),
                __uint_as_float(cvt_tf32(x.w - __uint_as_float(h3))));
            *(float4*)&Sh[r*72 + c4] = make_float4(
                __uint_as_float(h0), __uint_as_float(h1),
                __uint_as_float(h2), __uint_as_float(h3));
            *(float4*)&Sl[r*72 + c4] = lo;
        }
        __syncthreads();

#pragma unroll
        for (int ks = 0; ks < 8; ks++) {
            const size_t c0 = (size_t)kt*KTILE + ks*8 + tig;
            float s0 = srow[(size_t)r0 * SEQ + c0];
            float s1 = srow[(size_t)r1 * SEQ + c0];
            float s2 = srow[(size_t)r0 * SEQ + c0 + 4];
            float s3 = srow[(size_t)r1 * SEQ + c0 + 4];
            float e0 = __expf(s0 - mrow[0]) * inv0;
            float e1 = __expf(s1 - mrow[1]) * inv1;
            float e2 = __expf(s2 - mrow[0]) * inv0;
            float e3 = __expf(s3 - mrow[1]) * inv1;
            arow[(size_t)r0 * SEQ + c0]     = e0;
            arow[(size_t)r1 * SEQ + c0]     = e1;
            arow[(size_t)r0 * SEQ + c0 + 4] = e2;
            arow[(size_t)r1 * SEQ + c0 + 4] = e3;
            uint32_t aeh[4], ael[4];
            aeh[0] = cvt_tf32(e0); ael[0] = cvt_tf32(e0 - __uint_as_float(aeh[0]));
            aeh[1] = cvt_tf32(e1); ael[1] = cvt_tf32(e1 - __uint_as_float(aeh[1]));
            aeh[2] = cvt_tf32(e2); ael[2] = cvt_tf32(e2 - __uint_as_float(aeh[2]));
            aeh[3] = cvt_tf32(e3); ael[3] = cvt_tf32(e3 - __uint_as_float(aeh[3]));
#pragma unroll
            for (int nt = 0; nt < 8; nt++) {
                uint32_t bhv[2], blv[2];
                bhv[0] = __float_as_uint(Sh[(ks*8 + tig)*72 + nt*8 + g]);
                bhv[1] = __float_as_uint(Sh[(ks*8 + tig + 4)*72 + nt*8 + g]);
                blv[0] = __float_as_uint(Sl[(ks*8 + tig)*72 + nt*8 + g]);
                blv[1] = __float_as_uint(Sl[(ks*8 + tig + 4)*72 + nt*8 + g]);
                mma8(co[nt], aeh, bhv);
                mma8(co[nt], aeh, blv);
                mma8(co[nt], ael, bhv);
            }
        }
    }

    // write ctx [B,S,D]
#pragma unroll
    for (int nt = 0; nt < 8; nt++) {
        int d = nt*8 + tig*2;
        *(float2*)&g_ctx[((size_t)(b*SEQ) + qr0 + r0) * DMODEL + h*DK + d] =
            make_float2(co[nt][0], co[nt][1]);
        *(float2*)&g_ctx[((size_t)(b*SEQ) + qr0 + r1) * DMODEL + h*DK + d] =
            make_float2(co[nt][2], co[nt][3]);
    }
}

// ============================================================================
extern "C" void kernel_launch(void* const* d_in, const int* in_sizes, int n_in,
                              void* d_out, int out_size)
{
    const float* Q  = (const float*)d_in[0];
    const float* K  = (const float*)d_in[1];
    const float* V  = (const float*)d_in[2];
    const unsigned char* mask = (const unsigned char*)d_in[3];
    const float* Wq = (const float*)d_in[4];  const float* bq = (const float*)d_in[5];
    const float* Wk = (const float*)d_in[6];  const float* bk = (const float*)d_in[7];
    const float* Wv = (const float*)d_in[8];  const float* bv = (const float*)d_in[9];
    const float* Wo = (const float*)d_in[10]; const float* bo = (const float*)d_in[11];

    float* out    = (float*)d_out;
    float* attn   = out + (size_t)NTOK * DMODEL;
    float* scores = attn + (size_t)BATCH * NHEADS * SEQ * SEQ;

    cudaFuncSetAttribute(k_attn_mma, cudaFuncAttributeMaxDynamicSharedMemorySize,
                         ATTN_SMEM);

    dim3 gp(NTOK / 128, DMODEL / 128, 3);       // 32 x 8 x 3
    k_projmma<<<gp, 256>>>(Q, K, V, Wq, Wk, Wv, bq, bk, bv);

    dim3 gf(SEQ / 128, BATCH * NHEADS);         // 16 x 32
    k_attn_mma<<<gf, 256, ATTN_SMEM>>>(mask, scores, attn);

    dim3 go(NTOK / 128, DMODEL / 128);          // 32 x 8
    k_outmma<<<go, 256>>>(Wo, bo, Q, out);
}